// round 1
// baseline (speedup 1.0000x reference)
#include <cuda_runtime.h>
#include <cstdint>

// Problem constants
#define PB    8
#define PL    16384
#define PCIN  256
#define PCOUT 256
#define PS    4
#define PH    4
#define PD    64
#define PLS   4096   // L/S

// ---------------- scratch (no allocations allowed) ----------------
__device__ float g_xp  [PB * PLS * PCIN];       // pooled input (B, LS, CIN)      32 MB
__device__ float g_xaT [PB * PCOUT * PLS];      // x_a transposed (B, j, l)       32 MB
__device__ float g_xbT [PB * PCOUT * PLS];      // x_b transposed (B, j, l)       32 MB
__device__ float g_s   [PB * PCOUT];            // scale s_b[j'], j' = d*H + h
__device__ float g_Weff[PB * PCOUT * PCOUT];    // per-batch effective weight
__device__ float g_beff[PB * PCOUT];            // per-batch effective bias

// ---------------- kernel 1: max-pool over S=4 ----------------
// xp[b, ls, c] = max_{s<4} x[b, 4*ls+s, c]   (vectorized float4 over channels)
__global__ void pool_k(const float* __restrict__ x) {
    int idx = blockIdx.x * blockDim.x + threadIdx.x;      // over B*LS*64 float4s
    if (idx >= PB * PLS * (PCIN / 4)) return;
    const float4* px = (const float4*)x + (size_t)(idx >> 6) * 256 + (idx & 63);
    float4 a = px[0], b = px[64], c = px[128], d = px[192];
    float4 r;
    r.x = fmaxf(fmaxf(a.x, b.x), fmaxf(c.x, d.x));
    r.y = fmaxf(fmaxf(a.y, b.y), fmaxf(c.y, d.y));
    r.z = fmaxf(fmaxf(a.z, b.z), fmaxf(c.z, d.z));
    r.w = fmaxf(fmaxf(a.w, b.w), fmaxf(c.w, d.w));
    ((float4*)g_xp)[idx] = r;
}

// ---------------- kernel 2: x_a / x_b GEMMs, transposed store ----------------
// A = g_xp (32768 x 256), W (256 x 256), store xT[(b*256 + n)*4096 + l]
__global__ __launch_bounds__(256) void gemm_ab(
    const float* __restrict__ Wa, const float* __restrict__ ba,
    const float* __restrict__ Wb, const float* __restrict__ bb)
{
    const int which = blockIdx.z;
    const float* W    = which ? Wb : Wa;
    const float* bias = which ? bb : ba;
    float* outT       = which ? g_xbT : g_xaT;
    const float* A = g_xp;

    const int m0 = blockIdx.x * 128;
    const int n0 = blockIdx.y * 128;
    __shared__ float As[8][128];
    __shared__ float Bs[8][128];

    const int t  = threadIdx.x;
    const int tm = t & 15;    // M dim (16 lanes -> contiguous l on store)
    const int tn = t >> 4;    // N dim

    float acc[8][8];
#pragma unroll
    for (int i = 0; i < 8; i++)
#pragma unroll
        for (int j = 0; j < 8; j++) acc[i][j] = 0.0f;

    const int ar  = t >> 1;         // 0..127
    const int ak  = (t & 1) * 4;    // 0 / 4
    const int bk  = t >> 5;         // 0..7
    const int bc4 = (t & 31) * 4;   // 0..124

    for (int k0 = 0; k0 < 256; k0 += 8) {
        float4 av = *(const float4*)(A + (size_t)(m0 + ar) * 256 + k0 + ak);
        float4 bv = *(const float4*)(W + (size_t)(k0 + bk) * 256 + n0 + bc4);
        As[ak + 0][ar] = av.x; As[ak + 1][ar] = av.y;
        As[ak + 2][ar] = av.z; As[ak + 3][ar] = av.w;
        *(float4*)&Bs[bk][bc4] = bv;
        __syncthreads();
#pragma unroll
        for (int k = 0; k < 8; k++) {
            float af[8], bf[8];
#pragma unroll
            for (int i = 0; i < 8; i++) af[i] = As[k][tm + 16 * i];
#pragma unroll
            for (int j = 0; j < 8; j++) bf[j] = Bs[k][tn + 16 * j];
#pragma unroll
            for (int i = 0; i < 8; i++)
#pragma unroll
                for (int j = 0; j < 8; j++) acc[i][j] += af[i] * bf[j];
        }
        __syncthreads();
    }

#pragma unroll
    for (int j = 0; j < 8; j++) {
        const int n = n0 + tn + 16 * j;
        const float bi = bias[n];
#pragma unroll
        for (int i = 0; i < 8; i++) {
            const int m = m0 + tm + 16 * i;
            const int bidx = m >> 12;        // LS = 4096
            const int l    = m & 4095;
            outT[((size_t)(bidx << 8) + n) * 4096 + l] = acc[i][j] + bi;
        }
    }
}

// ---------------- block reductions ----------------
__device__ __forceinline__ float blockSum256(float v, float* red) {
    const int t = threadIdx.x;
#pragma unroll
    for (int o = 16; o > 0; o >>= 1) v += __shfl_xor_sync(0xffffffffu, v, o);
    if ((t & 31) == 0) red[t >> 5] = v;
    __syncthreads();
    if (t < 32) {
        float x = (t < 8) ? red[t] : 0.0f;
#pragma unroll
        for (int o = 4; o > 0; o >>= 1) x += __shfl_xor_sync(0xffffffffu, x, o);
        if (t == 0) red[0] = x;
    }
    __syncthreads();
    float r = red[0];
    __syncthreads();
    return r;
}

__device__ __forceinline__ float blockMax256(float v, float* red) {
    const int t = threadIdx.x;
#pragma unroll
    for (int o = 16; o > 0; o >>= 1) v = fmaxf(v, __shfl_xor_sync(0xffffffffu, v, o));
    if ((t & 31) == 0) red[t >> 5] = v;
    __syncthreads();
    if (t < 32) {
        float x = (t < 8) ? red[t] : -3.402823466e38f;
#pragma unroll
        for (int o = 4; o > 0; o >>= 1) x = fmaxf(x, __shfl_xor_sync(0xffffffffu, x, o));
        if (t == 0) red[0] = x;
    }
    __syncthreads();
    float r = red[0];
    __syncthreads();
    return r;
}

// ---------------- kernel 3: softmax over l + rolled reduction ----------------
// For each (b, j=h*D+d):  p = softmax_l(x_a[b,:,j])
//   x_ab = sum_l p[l] * (x_b[b,l,j] - x_b[b,(l+d)%LS, j])
// stored permuted: g_s[b*256 + d*H + h]
__global__ __launch_bounds__(256) void softmax_reduce() {
    const int bj = blockIdx.x;                 // = b*256 + j
    const float* arow = g_xaT + (size_t)bj * 4096;
    const float* brow = g_xbT + (size_t)bj * 4096;
    __shared__ float sE[4096];
    __shared__ float red[32];
    const int t = threadIdx.x;

    float mx = -3.402823466e38f;
#pragma unroll 4
    for (int i = t; i < 1024; i += 256) {
        float4 v = ((const float4*)arow)[i];
        ((float4*)sE)[i] = v;
        mx = fmaxf(mx, fmaxf(fmaxf(v.x, v.y), fmaxf(v.z, v.w)));
    }
    mx = blockMax256(mx, red);

    float sum = 0.0f;
#pragma unroll 4
    for (int i = t; i < 1024; i += 256) {
        float4 v = ((float4*)sE)[i];
        v.x = __expf(v.x - mx); v.y = __expf(v.y - mx);
        v.z = __expf(v.z - mx); v.w = __expf(v.w - mx);
        ((float4*)sE)[i] = v;
        sum += (v.x + v.y) + (v.z + v.w);
    }
    sum = blockSum256(sum, red);
    const float inv = 1.0f / sum;

    const int j = bj & 255;
    const int d = j & 63;
    const int h = j >> 6;

    float accv = 0.0f;
#pragma unroll 4
    for (int l = t; l < 4096; l += 256) {
        const float p = sE[l];
        accv += p * (brow[l] - brow[(l + d) & 4095]);
    }
    accv = blockSum256(accv, red);
    if (t == 0) g_s[(bj & ~255) + d * 4 + h] = accv * inv;
}

// ---------------- kernel 4: W_eff[b] = Wc_perm * diag(s_b) @ Wo ----------------
// perm(j') = (j'%H)*D + j'//H ;  64x64 tiles, 4x4 microtile
__global__ __launch_bounds__(256) void build_weff(
    const float* __restrict__ Wc, const float* __restrict__ Wo)
{
    const int b  = blockIdx.z;
    const int o0 = blockIdx.x * 64;
    const int i0 = blockIdx.y * 64;
    const float* s = g_s + b * 256;

    __shared__ float As[16][65];
    __shared__ float Bs[16][64];

    const int t  = threadIdx.x;
    const int tx = t & 15;   // o
    const int ty = t >> 4;   // i

    float acc[4][4];
#pragma unroll
    for (int i = 0; i < 4; i++)
#pragma unroll
        for (int j = 0; j < 4; j++) acc[i][j] = 0.0f;

    for (int k0 = 0; k0 < 256; k0 += 16) {
        const int kk = t & 15;
        const int kglob = k0 + kk;
        const float sv = s[kglob];
        const int pc = ((kglob & 3) << 6) + (kglob >> 2);   // perm column of Wc
#pragma unroll
        for (int r = 0; r < 4; r++) {
            const int irow = (t >> 4) * 4 + r;
            As[kk][irow] = Wc[(size_t)(i0 + irow) * 256 + pc] * sv;
        }
        *(float4*)&Bs[t >> 4][(t & 15) * 4] =
            *(const float4*)(Wo + (size_t)(k0 + (t >> 4)) * 256 + o0 + (t & 15) * 4);
        __syncthreads();
#pragma unroll
        for (int k = 0; k < 16; k++) {
            float af[4], bf[4];
#pragma unroll
            for (int i = 0; i < 4; i++) af[i] = As[k][ty + 16 * i];
#pragma unroll
            for (int j = 0; j < 4; j++) bf[j] = Bs[k][tx + 16 * j];
#pragma unroll
            for (int i = 0; i < 4; i++)
#pragma unroll
                for (int j = 0; j < 4; j++) acc[i][j] += af[i] * bf[j];
        }
        __syncthreads();
    }

#pragma unroll
    for (int i = 0; i < 4; i++)
#pragma unroll
        for (int j = 0; j < 4; j++)
            g_Weff[(size_t)b * 65536 + (size_t)(i0 + ty + 16 * i) * 256 + o0 + tx + 16 * j] = acc[i][j];
}

// beff[b][o] = sum_j' bc[perm(j')]*s_b[j']*Wo[j'][o] + bo[o]
__global__ void build_beff(const float* __restrict__ bc,
                           const float* __restrict__ Wo,
                           const float* __restrict__ bo)
{
    const int b = blockIdx.x;
    const int o = threadIdx.x;
    const float* s = g_s + b * 256;
    float acc = bo[o];
    for (int k = 0; k < 256; k++) {
        const int pc = ((k & 3) << 6) + (k >> 2);
        acc += bc[pc] * s[k] * Wo[(size_t)k * 256 + o];
    }
    g_beff[b * 256 + o] = acc;
}

// ---------------- kernel 5: out[b] = x[b] @ W_eff[b] + beff[b] ----------------
__global__ __launch_bounds__(256) void gemm_main(const float* __restrict__ x,
                                                 float* __restrict__ out)
{
    const int bz = blockIdx.z;
    const float* A    = x + (size_t)bz * PL * PCIN;
    const float* W    = g_Weff + (size_t)bz * 65536;
    const float* bias = g_beff + bz * 256;
    float* C          = out + (size_t)bz * PL * PCOUT;

    const int m0 = blockIdx.x * 128;
    const int n0 = blockIdx.y * 128;
    __shared__ float As[8][128];
    __shared__ float Bs[8][128];

    const int t  = threadIdx.x;
    const int tx = t & 15;    // N dim (coalesced store)
    const int ty = t >> 4;    // M dim

    float acc[8][8];
#pragma unroll
    for (int i = 0; i < 8; i++)
#pragma unroll
        for (int j = 0; j < 8; j++) acc[i][j] = 0.0f;

    const int ar  = t >> 1;
    const int ak  = (t & 1) * 4;
    const int bk  = t >> 5;
    const int bc4 = (t & 31) * 4;

    for (int k0 = 0; k0 < 256; k0 += 8) {
        float4 av = *(const float4*)(A + (size_t)(m0 + ar) * 256 + k0 + ak);
        float4 bv = *(const float4*)(W + (size_t)(k0 + bk) * 256 + n0 + bc4);
        As[ak + 0][ar] = av.x; As[ak + 1][ar] = av.y;
        As[ak + 2][ar] = av.z; As[ak + 3][ar] = av.w;
        *(float4*)&Bs[bk][bc4] = bv;
        __syncthreads();
#pragma unroll
        for (int k = 0; k < 8; k++) {
            float af[8], bf[8];
#pragma unroll
            for (int i = 0; i < 8; i++) af[i] = As[k][ty + 16 * i];
#pragma unroll
            for (int j = 0; j < 8; j++) bf[j] = Bs[k][tx + 16 * j];
#pragma unroll
            for (int i = 0; i < 8; i++)
#pragma unroll
                for (int j = 0; j < 8; j++) acc[i][j] += af[i] * bf[j];
        }
        __syncthreads();
    }

#pragma unroll
    for (int j = 0; j < 8; j++) {
        const int n = n0 + tx + 16 * j;
        const float bi = bias[n];
#pragma unroll
        for (int i = 0; i < 8; i++) {
            const int m = m0 + ty + 16 * i;
            C[(size_t)m * 256 + n] = acc[i][j] + bi;
        }
    }
}

// ---------------- launch ----------------
extern "C" void kernel_launch(void* const* d_in, const int* in_sizes, int n_in,
                              void* d_out, int out_size)
{
    const float* x  = (const float*)d_in[0];
    const float* Wa = (const float*)d_in[1];
    const float* ba = (const float*)d_in[2];
    const float* Wb = (const float*)d_in[3];
    const float* bb = (const float*)d_in[4];
    const float* Wc = (const float*)d_in[5];
    const float* bc = (const float*)d_in[6];
    const float* Wo = (const float*)d_in[7];
    const float* bo = (const float*)d_in[8];
    float* out = (float*)d_out;

    // 1) pool: B*LS*64 float4 threads
    pool_k<<<(PB * PLS * (PCIN / 4) + 255) / 256, 256>>>(x);

    // 2) x_a / x_b GEMMs with transposed store
    gemm_ab<<<dim3(256, 2, 2), 256>>>(Wa, ba, Wb, bb);

    // 3) softmax + rolled reduction -> g_s
    softmax_reduce<<<PB * PCOUT, 256>>>();

    // 4) effective per-batch weight + bias
    build_weff<<<dim3(4, 4, PB), 256>>>(Wc, Wo);
    build_beff<<<PB, 256>>>(bc, Wo, bo);

    // 5) main batched GEMM
    gemm_main<<<dim3(PL / 128, PCOUT / 128, PB), 256>>>(x, out);
}

// round 3
// speedup vs baseline: 2.1144x; 2.1144x over previous
#include <cuda_runtime.h>
#include <cuda_bf16.h>
#include <cstdint>

// Problem constants
#define PB    8
#define PL    16384
#define PCIN  256
#define PCOUT 256
#define PS    4
#define PH    4
#define PD    64
#define PLS   4096   // L/S

// ======================= scratch =======================
__device__ __nv_bfloat16 g_xhi [PB * PL * PCIN];     // x hi (B*L, 256)
__device__ __nv_bfloat16 g_xlo [PB * PL * PCIN];     // x lo
__device__ __nv_bfloat16 g_xphi[PB * PLS * PCIN];    // pooled hi (B*LS, 256)
__device__ __nv_bfloat16 g_xplo[PB * PLS * PCIN];    // pooled lo
__device__ __nv_bfloat16 g_WaT_hi[PCOUT * PCIN], g_WaT_lo[PCOUT * PCIN];   // [n][k]
__device__ __nv_bfloat16 g_WbT_hi[PCOUT * PCIN], g_WbT_lo[PCOUT * PCIN];
__device__ float        g_WcPT[PCOUT * PCIN];        // WcPT[k][i] = Wc[i][perm(k)]
__device__ float        g_xaT [PB * PCOUT * PLS];    // (b, j, l) fp32
__device__ float        g_xbT [PB * PCOUT * PLS];
__device__ float        g_s   [PB * PCOUT];
__device__ __nv_bfloat16 g_WeffT_hi[PB * PCOUT * PCOUT];  // [b][n][k]
__device__ __nv_bfloat16 g_WeffT_lo[PB * PCOUT * PCOUT];
__device__ float        g_beff[PB * PCOUT];

// ======================= PTX helpers (family-portable: sm_80-era) =======================
__device__ __forceinline__ uint32_t smem_to_u32(const void* p) {
    uint32_t a;
    asm("{ .reg .u64 t; cvta.to.shared.u64 t, %1; cvt.u32.u64 %0, t; }" : "=r"(a) : "l"(p));
    return a;
}
__device__ __forceinline__ void cp16(uint32_t saddr, const void* g) {
    asm volatile("cp.async.cg.shared.global [%0], [%1], 16;" :: "r"(saddr), "l"(g));
}
#define CP_COMMIT() asm volatile("cp.async.commit_group;" ::: "memory")
#define CP_WAIT(n)  asm volatile("cp.async.wait_group %0;" :: "n"(n) : "memory")

__device__ __forceinline__ void ldm_x4(uint32_t* d, uint32_t addr) {
    asm volatile("ldmatrix.sync.aligned.m8n8.x4.shared.b16 {%0,%1,%2,%3}, [%4];"
        : "=r"(d[0]), "=r"(d[1]), "=r"(d[2]), "=r"(d[3]) : "r"(addr));
}
__device__ __forceinline__ void mma_bf16(float* c, const uint32_t* a, const uint32_t* b) {
    asm volatile("mma.sync.aligned.m16n8k16.row.col.f32.bf16.bf16.f32 "
        "{%0,%1,%2,%3}, {%4,%5,%6,%7}, {%8,%9}, {%0,%1,%2,%3};"
        : "+f"(c[0]), "+f"(c[1]), "+f"(c[2]), "+f"(c[3])
        : "r"(a[0]), "r"(a[1]), "r"(a[2]), "r"(a[3]), "r"(b[0]), "r"(b[1]));
}

// ======================= split helpers =======================
__device__ __forceinline__ uint32_t pack_bf(__nv_bfloat16 a, __nv_bfloat16 b) {
    return (uint32_t)__bfloat16_as_ushort(a) | ((uint32_t)__bfloat16_as_ushort(b) << 16);
}
__device__ __forceinline__ void split4(float4 v, uint2& h, uint2& l) {
    __nv_bfloat16 h0 = __float2bfloat16(v.x), h1 = __float2bfloat16(v.y);
    __nv_bfloat16 h2 = __float2bfloat16(v.z), h3 = __float2bfloat16(v.w);
    __nv_bfloat16 l0 = __float2bfloat16(v.x - __bfloat162float(h0));
    __nv_bfloat16 l1 = __float2bfloat16(v.y - __bfloat162float(h1));
    __nv_bfloat16 l2 = __float2bfloat16(v.z - __bfloat162float(h2));
    __nv_bfloat16 l3 = __float2bfloat16(v.w - __bfloat162float(h3));
    h.x = pack_bf(h0, h1); h.y = pack_bf(h2, h3);
    l.x = pack_bf(l0, l1); l.y = pack_bf(l2, l3);
}

// ===== kernel 1: pool + fp32 -> bf16 split conversion =====
__global__ void pool_convert(const float* __restrict__ x) {
    int idx = blockIdx.x * blockDim.x + threadIdx.x;   // B*LS*64
    if (idx >= PB * PLS * 64) return;
    int rowp = idx >> 6, c4 = idx & 63;
    const float4* px = (const float4*)x + (size_t)rowp * 256 + c4;
    uint2* xh = (uint2*)g_xhi; uint2* xl = (uint2*)g_xlo;
    float4 v[4];
#pragma unroll
    for (int s = 0; s < 4; ++s) {
        v[s] = px[(size_t)s * 64];
        uint2 h, l; split4(v[s], h, l);
        size_t o = (size_t)(rowp * 4 + s) * 64 + c4;
        xh[o] = h; xl[o] = l;
    }
    float4 r;
    r.x = fmaxf(fmaxf(v[0].x, v[1].x), fmaxf(v[2].x, v[3].x));
    r.y = fmaxf(fmaxf(v[0].y, v[1].y), fmaxf(v[2].y, v[3].y));
    r.z = fmaxf(fmaxf(v[0].z, v[1].z), fmaxf(v[2].z, v[3].z));
    r.w = fmaxf(fmaxf(v[0].w, v[1].w), fmaxf(v[2].w, v[3].w));
    uint2 h, l; split4(r, h, l);
    ((uint2*)g_xphi)[(size_t)rowp * 64 + c4] = h;
    ((uint2*)g_xplo)[(size_t)rowp * 64 + c4] = l;
}

// ===== kernel 2: weight prep (transpose + split; Wc permute-transpose) =====
__global__ void prep_w(const float* __restrict__ Wa, const float* __restrict__ Wb,
                       const float* __restrict__ Wc) {
    __shared__ float tile[32][33];
    const int zm = blockIdx.z;
    const int j0 = blockIdx.x * 32, i0 = blockIdx.y * 32;
    const float* src = (zm == 0) ? Wa : (zm == 1) ? Wb : Wc;
    for (int r = threadIdx.y; r < 32; r += 8)
        tile[r][threadIdx.x] = src[(size_t)(i0 + r) * 256 + j0 + threadIdx.x];
    __syncthreads();
    for (int r = threadIdx.y; r < 32; r += 8) {
        int j = j0 + r;
        float val = tile[threadIdx.x][r];           // = src[i0+tx][j]
        int i = i0 + threadIdx.x;
        if (zm == 2) {
            int k = ((j & 63) << 2) | (j >> 6);     // inverse of perm
            g_WcPT[(size_t)k * 256 + i] = val;
        } else {
            __nv_bfloat16 h = __float2bfloat16(val);
            __nv_bfloat16 l = __float2bfloat16(val - __bfloat162float(h));
            if (zm == 0) { g_WaT_hi[(size_t)j * 256 + i] = h; g_WaT_lo[(size_t)j * 256 + i] = l; }
            else         { g_WbT_hi[(size_t)j * 256 + i] = h; g_WbT_lo[(size_t)j * 256 + i] = l; }
        }
    }
}

// ======================= HMMA GEMM core =======================
// CTA: 128(M) x 128(N), K'=768 = 12 slabs of 64 (3-term bf16 split folded into K).
// SMEM: A/B slabs, 128 rows x (128B data + 16B pad) = 18432B each, double buffered.
#define SLAB_BYTES 18432
#define SA0 0
#define SB0 18432
#define SA1 36864
#define SB1 55296
#define GEMM_SMEM 73728

// load one slab: A rows m0..m0+127 (already offset), B rows n0..n0+127, 64 halves each
__device__ __forceinline__ void load_slab(uint32_t sA, uint32_t sB, int t,
                                          const __nv_bfloat16* Ag, const __nv_bfloat16* Bg) {
#pragma unroll
    for (int i = 0; i < 4; ++i) {
        int lin = i * 256 + t;
        int r = lin >> 3, ch = lin & 7;
        cp16(sA + r * 144 + ch * 16, Ag + (size_t)r * 256 + ch * 8);
        cp16(sB + r * 144 + ch * 16, Bg + (size_t)r * 256 + ch * 8);
    }
}

__device__ __forceinline__ void compute_slab(uint32_t sA, uint32_t sB,
    int warp_m, int warp_n, int lane, float acc[2][8][4])
{
    const int lrow  = lane & 15;
    const int lcolA = (lane >> 4) * 16;
    const int nrow  = (lane & 7) + ((lane >> 4) << 3);
    const int kcolB = ((lane >> 3) & 1) * 16;
#pragma unroll
    for (int ks = 0; ks < 4; ++ks) {
        uint32_t a[2][4];
        ldm_x4(a[0], sA + (warp_m * 32 +      lrow) * 144 + ks * 32 + lcolA);
        ldm_x4(a[1], sA + (warp_m * 32 + 16 + lrow) * 144 + ks * 32 + lcolA);
        uint32_t b[4][4];
#pragma unroll
        for (int nb = 0; nb < 4; ++nb)
            ldm_x4(b[nb], sB + (warp_n * 64 + nb * 16 + nrow) * 144 + ks * 32 + kcolB);
#pragma unroll
        for (int ms = 0; ms < 2; ++ms)
#pragma unroll
            for (int nb = 0; nb < 4; ++nb) {
                mma_bf16(acc[ms][nb * 2 + 0], a[ms], &b[nb][0]);
                mma_bf16(acc[ms][nb * 2 + 1], a[ms], &b[nb][2]);
            }
    }
}

// slab source selection for the 3-term split:
//   s in [0,4):  Ah x Bh ; s in [4,8): Ah x Bl ; s in [8,12): Al x Bh ; kc = (s&3)*64
__device__ __forceinline__ const __nv_bfloat16* a_sel(int s, const __nv_bfloat16* Ah,
                                                      const __nv_bfloat16* Al, size_t row0) {
    return ((s < 8) ? Ah : Al) + row0 * 256 + ((s & 3) << 6);
}
__device__ __forceinline__ const __nv_bfloat16* b_sel(int s, const __nv_bfloat16* Bh,
                                                      const __nv_bfloat16* Bl, size_t row0) {
    return ((s >= 4 && s < 8) ? Bl : Bh) + row0 * 256 + ((s & 3) << 6);
}

// ===== kernel 3: x_a/x_b GEMM with transposed fp32 store =====
__global__ __launch_bounds__(256, 2) void tc_gemm_ab(const float* __restrict__ ba,
                                                     const float* __restrict__ bb) {
    extern __shared__ char smem[];
    uint32_t sb = smem_to_u32(smem);
    const int t = threadIdx.x, lane = t & 31, wid = t >> 5;
    const int warp_m = wid & 3, warp_n = wid >> 2;
    const int m0 = blockIdx.x * 128;
    const int which = blockIdx.y >> 1;
    const int n0 = (blockIdx.y & 1) * 128;

    const __nv_bfloat16* Bh = which ? g_WbT_hi : g_WaT_hi;
    const __nv_bfloat16* Bl = which ? g_WbT_lo : g_WaT_lo;

    float acc[2][8][4];
#pragma unroll
    for (int i = 0; i < 2; ++i)
#pragma unroll
        for (int j = 0; j < 8; ++j)
#pragma unroll
            for (int k = 0; k < 4; ++k) acc[i][j][k] = 0.0f;

    load_slab(sb + SA0, sb + SB0, t, a_sel(0, g_xphi, g_xplo, m0), b_sel(0, Bh, Bl, n0));
    CP_COMMIT();
    for (int s = 0; s < 12; ++s) {
        uint32_t cA = sb + ((s & 1) ? SA1 : SA0);
        uint32_t cB = sb + ((s & 1) ? SB1 : SB0);
        if (s + 1 < 12) {
            load_slab(sb + ((s & 1) ? SA0 : SA1), sb + ((s & 1) ? SB0 : SB1), t,
                      a_sel(s + 1, g_xphi, g_xplo, m0), b_sel(s + 1, Bh, Bl, n0));
            CP_COMMIT();
            CP_WAIT(1);
        } else {
            CP_WAIT(0);
        }
        __syncthreads();
        compute_slab(cA, cB, warp_m, warp_n, lane, acc);
        __syncthreads();
    }

    // stage C in smem, then coalesced transposed store
    float* Cs = (float*)smem;                       // [128][129]
    const int g = lane >> 2, tt2 = (lane & 3) * 2;
#pragma unroll
    for (int ms = 0; ms < 2; ++ms)
#pragma unroll
        for (int nb8 = 0; nb8 < 8; ++nb8) {
            int ml = warp_m * 32 + ms * 16 + g;
            int nl = warp_n * 64 + nb8 * 8 + tt2;
            Cs[ml * 129 + nl]           = acc[ms][nb8][0];
            Cs[ml * 129 + nl + 1]       = acc[ms][nb8][1];
            Cs[(ml + 8) * 129 + nl]     = acc[ms][nb8][2];
            Cs[(ml + 8) * 129 + nl + 1] = acc[ms][nb8][3];
        }
    __syncthreads();

    const int b = m0 >> 12, l0 = m0 & 4095;
    float* outT = which ? g_xbT : g_xaT;
    const float* bias = which ? bb : ba;
    for (int i = 0; i < 64; ++i) {
        int lin = i * 256 + t;
        int n = lin >> 7, l = lin & 127;
        outT[(size_t)((b << 8) + n0 + n) * 4096 + l0 + l] = Cs[l * 129 + n] + bias[n0 + n];
    }
}

// ===== kernel 6: main GEMM out = x @ Weff[b] + beff[b] =====
__global__ __launch_bounds__(256, 2) void tc_gemm_main(float* __restrict__ out) {
    extern __shared__ char smem[];
    uint32_t sb = smem_to_u32(smem);
    const int t = threadIdx.x, lane = t & 31, wid = t >> 5;
    const int warp_m = wid & 3, warp_n = wid >> 2;
    const int m0 = blockIdx.x * 128;
    const int n0 = blockIdx.y * 128;
    const int bz = m0 >> 14;

    const __nv_bfloat16* Bh = g_WeffT_hi + (size_t)bz * 65536;
    const __nv_bfloat16* Bl = g_WeffT_lo + (size_t)bz * 65536;

    float acc[2][8][4];
#pragma unroll
    for (int i = 0; i < 2; ++i)
#pragma unroll
        for (int j = 0; j < 8; ++j)
#pragma unroll
            for (int k = 0; k < 4; ++k) acc[i][j][k] = 0.0f;

    load_slab(sb + SA0, sb + SB0, t, a_sel(0, g_xhi, g_xlo, m0), b_sel(0, Bh, Bl, n0));
    CP_COMMIT();
    for (int s = 0; s < 12; ++s) {
        uint32_t cA = sb + ((s & 1) ? SA1 : SA0);
        uint32_t cB = sb + ((s & 1) ? SB1 : SB0);
        if (s + 1 < 12) {
            load_slab(sb + ((s & 1) ? SA0 : SA1), sb + ((s & 1) ? SB0 : SB1), t,
                      a_sel(s + 1, g_xhi, g_xlo, m0), b_sel(s + 1, Bh, Bl, n0));
            CP_COMMIT();
            CP_WAIT(1);
        } else {
            CP_WAIT(0);
        }
        __syncthreads();
        compute_slab(cA, cB, warp_m, warp_n, lane, acc);
        __syncthreads();
    }

    const float* bias = g_beff + (bz << 8);
    const int g = lane >> 2, tt2 = (lane & 3) * 2;
#pragma unroll
    for (int ms = 0; ms < 2; ++ms)
#pragma unroll
        for (int nb8 = 0; nb8 < 8; ++nb8) {
            int m = m0 + warp_m * 32 + ms * 16 + g;
            int n = n0 + warp_n * 64 + nb8 * 8 + tt2;
            float b0 = bias[n], b1 = bias[n + 1];
            float2 v0 = make_float2(acc[ms][nb8][0] + b0, acc[ms][nb8][1] + b1);
            float2 v1 = make_float2(acc[ms][nb8][2] + b0, acc[ms][nb8][3] + b1);
            *(float2*)&out[(size_t)m * 256 + n]       = v0;
            *(float2*)&out[(size_t)(m + 8) * 256 + n] = v1;
        }
}

// ===== block reductions =====
__device__ __forceinline__ float blockSum256(float v, float* red) {
    const int t = threadIdx.x;
#pragma unroll
    for (int o = 16; o > 0; o >>= 1) v += __shfl_xor_sync(0xffffffffu, v, o);
    if ((t & 31) == 0) red[t >> 5] = v;
    __syncthreads();
    if (t < 32) {
        float x = (t < 8) ? red[t] : 0.0f;
#pragma unroll
        for (int o = 4; o > 0; o >>= 1) x += __shfl_xor_sync(0xffffffffu, x, o);
        if (t == 0) red[0] = x;
    }
    __syncthreads();
    float r = red[0];
    __syncthreads();
    return r;
}
__device__ __forceinline__ float blockMax256(float v, float* red) {
    const int t = threadIdx.x;
#pragma unroll
    for (int o = 16; o > 0; o >>= 1) v = fmaxf(v, __shfl_xor_sync(0xffffffffu, v, o));
    if ((t & 31) == 0) red[t >> 5] = v;
    __syncthreads();
    if (t < 32) {
        float x = (t < 8) ? red[t] : -3.402823466e38f;
#pragma unroll
        for (int o = 4; o > 0; o >>= 1) x = fmaxf(x, __shfl_xor_sync(0xffffffffu, x, o));
        if (t == 0) red[0] = x;
    }
    __syncthreads();
    float r = red[0];
    __syncthreads();
    return r;
}

// ===== kernel 4: softmax over l + rolled reduction -> g_s =====
__global__ __launch_bounds__(256) void softmax_reduce() {
    const int bj = blockIdx.x;
    const float* arow = g_xaT + (size_t)bj * 4096;
    const float* brow = g_xbT + (size_t)bj * 4096;
    __shared__ float sE[4096];
    __shared__ float red[32];
    const int t = threadIdx.x;

    float mx = -3.402823466e38f;
#pragma unroll 4
    for (int i = t; i < 1024; i += 256) {
        float4 v = ((const float4*)arow)[i];
        ((float4*)sE)[i] = v;
        mx = fmaxf(mx, fmaxf(fmaxf(v.x, v.y), fmaxf(v.z, v.w)));
    }
    mx = blockMax256(mx, red);

    float sum = 0.0f;
#pragma unroll 4
    for (int i = t; i < 1024; i += 256) {
        float4 v = ((float4*)sE)[i];
        v.x = __expf(v.x - mx); v.y = __expf(v.y - mx);
        v.z = __expf(v.z - mx); v.w = __expf(v.w - mx);
        ((float4*)sE)[i] = v;
        sum += (v.x + v.y) + (v.z + v.w);
    }
    sum = blockSum256(sum, red);
    const float inv = 1.0f / sum;

    const int j = bj & 255;
    const int d = j & 63;
    const int h = j >> 6;

    float accv = 0.0f;
#pragma unroll 4
    for (int l = t; l < 4096; l += 256) {
        const float p = sE[l];
        accv += p * (brow[l] - brow[(l + d) & 4095]);
    }
    accv = blockSum256(accv, red);
    if (t == 0) g_s[(bj & ~255) + d * 4 + h] = accv * inv;
}

// ===== kernel 5: W_eff^T[b] (bf16 split) + beff =====
__global__ __launch_bounds__(256) void build_weff(const float* __restrict__ Wo) {
    const int b  = blockIdx.z;
    const int o0 = blockIdx.x * 64;
    const int i0 = blockIdx.y * 64;
    const float* s = g_s + b * 256;

    __shared__ float As[16][65];
    __shared__ float Bs[16][64];

    const int t  = threadIdx.x;
    const int tx = t & 15;
    const int ty = t >> 4;

    float acc[4][4];
#pragma unroll
    for (int i = 0; i < 4; i++)
#pragma unroll
        for (int j = 0; j < 4; j++) acc[i][j] = 0.0f;

    for (int k0 = 0; k0 < 256; k0 += 16) {
#pragma unroll
        for (int r = 0; r < 4; ++r) {
            int kk = (t >> 6) * 4 + r;
            int irow = t & 63;
            As[kk][irow] = g_WcPT[(size_t)(k0 + kk) * 256 + i0 + irow] * s[k0 + kk];
        }
        *(float4*)&Bs[t >> 4][(t & 15) * 4] =
            *(const float4*)(Wo + (size_t)(k0 + (t >> 4)) * 256 + o0 + (t & 15) * 4);
        __syncthreads();
#pragma unroll
        for (int k = 0; k < 16; k++) {
            float af[4], bf[4];
#pragma unroll
            for (int i = 0; i < 4; i++) af[i] = As[k][ty + 16 * i];
#pragma unroll
            for (int j = 0; j < 4; j++) bf[j] = Bs[k][tx + 16 * j];
#pragma unroll
            for (int i = 0; i < 4; i++)
#pragma unroll
                for (int j = 0; j < 4; j++) acc[i][j] += af[i] * bf[j];
        }
        __syncthreads();
    }

#pragma unroll
    for (int i = 0; i < 4; i++)
#pragma unroll
        for (int j = 0; j < 4; j++) {
            float v = acc[i][j];
            int o = o0 + tx + 16 * j;
            int irow = i0 + ty + 16 * i;
            __nv_bfloat16 h = __float2bfloat16(v);
            __nv_bfloat16 l = __float2bfloat16(v - __bfloat162float(h));
            g_WeffT_hi[(size_t)b * 65536 + (size_t)o * 256 + irow] = h;
            g_WeffT_lo[(size_t)b * 65536 + (size_t)o * 256 + irow] = l;
        }
}

__global__ void build_beff(const float* __restrict__ bc,
                           const float* __restrict__ Wo,
                           const float* __restrict__ bo) {
    const int b = blockIdx.x;
    const int o = threadIdx.x;
    const float* s = g_s + b * 256;
    float acc = bo[o];
    for (int k = 0; k < 256; k++) {
        const int pc = ((k & 3) << 6) + (k >> 2);
        acc += bc[pc] * s[k] * Wo[(size_t)k * 256 + o];
    }
    g_beff[b * 256 + o] = acc;
}

// ======================= launch =======================
extern "C" void kernel_launch(void* const* d_in, const int* in_sizes, int n_in,
                              void* d_out, int out_size)
{
    const float* x  = (const float*)d_in[0];
    const float* Wa = (const float*)d_in[1];
    const float* ba = (const float*)d_in[2];
    const float* Wb = (const float*)d_in[3];
    const float* bb = (const float*)d_in[4];
    const float* Wc = (const float*)d_in[5];
    const float* bc = (const float*)d_in[6];
    const float* Wo = (const float*)d_in[7];
    const float* bo = (const float*)d_in[8];
    float* out = (float*)d_out;

    cudaFuncSetAttribute(tc_gemm_ab,   cudaFuncAttributeMaxDynamicSharedMemorySize, GEMM_SMEM);
    cudaFuncSetAttribute(tc_gemm_main, cudaFuncAttributeMaxDynamicSharedMemorySize, GEMM_SMEM);

    pool_convert<<<PB * PLS * 64 / 256, 256>>>(x);
    prep_w<<<dim3(8, 8, 3), dim3(32, 8)>>>(Wa, Wb, Wc);
    tc_gemm_ab<<<dim3(256, 4), 256, GEMM_SMEM>>>(ba, bb);
    softmax_reduce<<<PB * PCOUT, 256>>>();
    build_weff<<<dim3(4, 4, PB), 256>>>(Wo);
    build_beff<<<PB, 256>>>(bc, Wo, bo);
    tc_gemm_main<<<dim3(PL * PB / 128, 2), 256, GEMM_SMEM>>>(out);
}

// round 4
// speedup vs baseline: 3.0802x; 1.4568x over previous
#include <cuda_runtime.h>
#include <cuda_fp16.h>
#include <cstdint>

// Problem constants
#define PB    8
#define PL    16384
#define PCIN  256
#define PCOUT 256
#define PS    4
#define PH    4
#define PD    64
#define PLS   4096   // L/S

// ======================= scratch =======================
__device__ __half g_xf16 [PB * PL * PCIN];      // x fp16 (B*L, 256)         67 MB
__device__ __half g_xpf16[PB * PLS * PCIN];     // pooled fp16 (B*LS, 256)   17 MB
__device__ __half g_WaT_h[PCOUT * PCIN], g_WaT_l[PCOUT * PCIN];   // [n][k] split
__device__ __half g_WbT_h[PCOUT * PCIN], g_WbT_l[PCOUT * PCIN];
__device__ float  g_WcPT[PCOUT * PCIN];          // WcPT[k][i] = Wc[i][perm(k)]
__device__ float  g_xaT [PB * PCOUT * PLS];      // (b, j, l) fp32
__device__ float  g_xbT [PB * PCOUT * PLS];
__device__ float  g_s   [PB * PCOUT];
__device__ __half g_WeffT_h[PB * PCOUT * PCOUT]; // [b][n][k] split
__device__ __half g_WeffT_l[PB * PCOUT * PCOUT];
__device__ float  g_beff[PB * PCOUT];

// ======================= PTX helpers (family-portable) =======================
__device__ __forceinline__ uint32_t smem_to_u32(const void* p) {
    uint32_t a;
    asm("{ .reg .u64 t; cvta.to.shared.u64 t, %1; cvt.u32.u64 %0, t; }" : "=r"(a) : "l"(p));
    return a;
}
__device__ __forceinline__ void cp16(uint32_t saddr, const void* g) {
    asm volatile("cp.async.cg.shared.global [%0], [%1], 16;" :: "r"(saddr), "l"(g));
}
#define CP_COMMIT() asm volatile("cp.async.commit_group;" ::: "memory")
#define CP_WAIT(n)  asm volatile("cp.async.wait_group %0;" :: "n"(n) : "memory")

__device__ __forceinline__ void ldm_x4(uint32_t* d, uint32_t addr) {
    asm volatile("ldmatrix.sync.aligned.m8n8.x4.shared.b16 {%0,%1,%2,%3}, [%4];"
        : "=r"(d[0]), "=r"(d[1]), "=r"(d[2]), "=r"(d[3]) : "r"(addr));
}
__device__ __forceinline__ void mma_f16(float* c, const uint32_t* a, const uint32_t* b) {
    asm volatile("mma.sync.aligned.m16n8k16.row.col.f32.f16.f16.f32 "
        "{%0,%1,%2,%3}, {%4,%5,%6,%7}, {%8,%9}, {%0,%1,%2,%3};"
        : "+f"(c[0]), "+f"(c[1]), "+f"(c[2]), "+f"(c[3])
        : "r"(a[0]), "r"(a[1]), "r"(a[2]), "r"(a[3]), "r"(b[0]), "r"(b[1]));
}

// XOR swizzle for 128B rows (8 chunks of 16B): conflict-free ldmatrix + cp.async
__device__ __forceinline__ uint32_t swz(int row, int chunk) {
    return (uint32_t)(row * 128 + (((chunk ^ row) & 7) << 4));
}

// ======================= conversion helpers =======================
__device__ __forceinline__ uint2 cvt4h(float4 v) {
    __half2 p0 = __floats2half2_rn(v.x, v.y);
    __half2 p1 = __floats2half2_rn(v.z, v.w);
    uint2 r;
    r.x = *(uint32_t*)&p0; r.y = *(uint32_t*)&p1;
    return r;
}

// ===== kernel 1: pool + fp32 -> fp16 conversion =====
__global__ void pool_convert(const float* __restrict__ x) {
    int idx = blockIdx.x * blockDim.x + threadIdx.x;   // B*LS*64
    if (idx >= PB * PLS * 64) return;
    int rowp = idx >> 6, c4 = idx & 63;
    const float4* px = (const float4*)x + (size_t)rowp * 256 + c4;
    uint2* xf = (uint2*)g_xf16;
    float4 v[4];
#pragma unroll
    for (int s = 0; s < 4; ++s) {
        v[s] = px[(size_t)s * 64];
        xf[(size_t)(rowp * 4 + s) * 64 + c4] = cvt4h(v[s]);
    }
    float4 r;
    r.x = fmaxf(fmaxf(v[0].x, v[1].x), fmaxf(v[2].x, v[3].x));
    r.y = fmaxf(fmaxf(v[0].y, v[1].y), fmaxf(v[2].y, v[3].y));
    r.z = fmaxf(fmaxf(v[0].z, v[1].z), fmaxf(v[2].z, v[3].z));
    r.w = fmaxf(fmaxf(v[0].w, v[1].w), fmaxf(v[2].w, v[3].w));
    ((uint2*)g_xpf16)[(size_t)rowp * 64 + c4] = cvt4h(r);
}

// ===== kernel 2: weight prep (transpose + fp16 split; Wc permute-transpose) =====
__global__ void prep_w(const float* __restrict__ Wa, const float* __restrict__ Wb,
                       const float* __restrict__ Wc) {
    __shared__ float tile[32][33];
    const int zm = blockIdx.z;
    const int j0 = blockIdx.x * 32, i0 = blockIdx.y * 32;
    const float* src = (zm == 0) ? Wa : (zm == 1) ? Wb : Wc;
    for (int r = threadIdx.y; r < 32; r += 8)
        tile[r][threadIdx.x] = src[(size_t)(i0 + r) * 256 + j0 + threadIdx.x];
    __syncthreads();
    for (int r = threadIdx.y; r < 32; r += 8) {
        int j = j0 + r;
        float val = tile[threadIdx.x][r];           // = src[i0+tx][j]
        int i = i0 + threadIdx.x;
        if (zm == 2) {
            int k = ((j & 63) << 2) | (j >> 6);     // inverse of perm
            g_WcPT[(size_t)k * 256 + i] = val;
        } else {
            __half h = __float2half_rn(val);
            __half l = __float2half_rn(val - __half2float(h));
            if (zm == 0) { g_WaT_h[(size_t)j * 256 + i] = h; g_WaT_l[(size_t)j * 256 + i] = l; }
            else         { g_WbT_h[(size_t)j * 256 + i] = h; g_WbT_l[(size_t)j * 256 + i] = l; }
        }
    }
}

// ======================= HMMA GEMM core =======================
// CTA: 128(M) x 128(N); K=256 in 4 chunks of 64.
// Per chunk: A (single fp16) used for BOTH Bh and Bl terms (out = A@(Bh+Bl)).
// SMEM tiles: 128 rows x 128B, XOR-swizzled -> 16 KB each; {A,Bh,Bl} x2 = 96 KB.
#define TILE_B 16384
#define SA(buf)  ((buf) * 49152 + 0)
#define SBH(buf) ((buf) * 49152 + 16384)
#define SBL(buf) ((buf) * 49152 + 32768)
#define GEMM_SMEM 98304

// load one 128x64-f16 tile (global ld = 256 halves)
__device__ __forceinline__ void load_tile(uint32_t s, int t, const __half* g) {
#pragma unroll
    for (int i = 0; i < 4; ++i) {
        int lin = i * 256 + t;
        int r = lin >> 3, ch = lin & 7;
        cp16(s + swz(r, ch), g + (size_t)r * 256 + ch * 8);
    }
}

__device__ __forceinline__ void load_chunk(uint32_t sb, int buf, int t, int c,
    const __half* A, const __half* Bh, const __half* Bl) {
    load_tile(sb + SA(buf),  t, A  + c * 64);
    load_tile(sb + SBH(buf), t, Bh + c * 64);
    load_tile(sb + SBL(buf), t, Bl + c * 64);
}

__device__ __forceinline__ void compute_chunk(uint32_t sA, uint32_t sBh, uint32_t sBl,
    int warp_m, int warp_n, int lane, float acc[2][8][4])
{
    const int lrow = lane & 15;
    const int ach  = lane >> 4;                 // 0/1
    const int nrow = (lane & 7) | ((lane >> 4) << 3);
    const int bch  = (lane >> 3) & 1;
#pragma unroll
    for (int ks = 0; ks < 4; ++ks) {
        uint32_t a[2][4];
        ldm_x4(a[0], sA + swz(warp_m * 32 +      lrow, ks * 2 + ach));
        ldm_x4(a[1], sA + swz(warp_m * 32 + 16 + lrow, ks * 2 + ach));
        uint32_t b[4][4];
#pragma unroll
        for (int nb = 0; nb < 4; ++nb)
            ldm_x4(b[nb], sBh + swz(warp_n * 64 + nb * 16 + nrow, ks * 2 + bch));
#pragma unroll
        for (int ms = 0; ms < 2; ++ms)
#pragma unroll
            for (int nb = 0; nb < 4; ++nb) {
                mma_f16(acc[ms][nb * 2 + 0], a[ms], &b[nb][0]);
                mma_f16(acc[ms][nb * 2 + 1], a[ms], &b[nb][2]);
            }
#pragma unroll
        for (int nb = 0; nb < 4; ++nb)
            ldm_x4(b[nb], sBl + swz(warp_n * 64 + nb * 16 + nrow, ks * 2 + bch));
#pragma unroll
        for (int ms = 0; ms < 2; ++ms)
#pragma unroll
            for (int nb = 0; nb < 4; ++nb) {
                mma_f16(acc[ms][nb * 2 + 0], a[ms], &b[nb][0]);
                mma_f16(acc[ms][nb * 2 + 1], a[ms], &b[nb][2]);
            }
    }
}

// ===== kernel 3: x_a/x_b GEMM with transposed fp32 store =====
__global__ __launch_bounds__(256, 2) void tc_gemm_ab(const float* __restrict__ ba,
                                                     const float* __restrict__ bb) {
    extern __shared__ char smem[];
    uint32_t sb = smem_to_u32(smem);
    const int t = threadIdx.x, lane = t & 31, wid = t >> 5;
    const int warp_m = wid & 3, warp_n = wid >> 2;
    const int which = blockIdx.x >> 1;
    const int n0 = (blockIdx.x & 1) * 128;
    const int m0 = blockIdx.y * 128;

    const __half* A  = g_xpf16 + (size_t)m0 * 256;
    const __half* Bh = (which ? g_WbT_h : g_WaT_h) + (size_t)n0 * 256;
    const __half* Bl = (which ? g_WbT_l : g_WaT_l) + (size_t)n0 * 256;

    float acc[2][8][4];
#pragma unroll
    for (int i = 0; i < 2; ++i)
#pragma unroll
        for (int j = 0; j < 8; ++j)
#pragma unroll
            for (int k = 0; k < 4; ++k) acc[i][j][k] = 0.0f;

    load_chunk(sb, 0, t, 0, A, Bh, Bl);
    CP_COMMIT();
    for (int c = 0; c < 4; ++c) {
        if (c + 1 < 4) {
            load_chunk(sb, (c + 1) & 1, t, c + 1, A, Bh, Bl);
            CP_COMMIT();
            CP_WAIT(1);
        } else {
            CP_WAIT(0);
        }
        __syncthreads();
        compute_chunk(sb + SA(c & 1), sb + SBH(c & 1), sb + SBL(c & 1),
                      warp_m, warp_n, lane, acc);
        __syncthreads();
    }

    // stage C in smem, then coalesced transposed store
    float* Cs = (float*)smem;                       // [128][129]
    const int g = lane >> 2, tt2 = (lane & 3) * 2;
#pragma unroll
    for (int ms = 0; ms < 2; ++ms)
#pragma unroll
        for (int nb8 = 0; nb8 < 8; ++nb8) {
            int ml = warp_m * 32 + ms * 16 + g;
            int nl = warp_n * 64 + nb8 * 8 + tt2;
            Cs[ml * 129 + nl]           = acc[ms][nb8][0];
            Cs[ml * 129 + nl + 1]       = acc[ms][nb8][1];
            Cs[(ml + 8) * 129 + nl]     = acc[ms][nb8][2];
            Cs[(ml + 8) * 129 + nl + 1] = acc[ms][nb8][3];
        }
    __syncthreads();

    const int b = m0 >> 12, l0 = m0 & 4095;
    float* outT = which ? g_xbT : g_xaT;
    const float* bias = which ? bb : ba;
    for (int i = 0; i < 64; ++i) {
        int lin = i * 256 + t;
        int n = lin >> 7, l = lin & 127;
        outT[(size_t)((b << 8) + n0 + n) * 4096 + l0 + l] = Cs[l * 129 + n] + bias[n0 + n];
    }
}

// ===== kernel 6: main GEMM out = x @ Weff[b] + beff[b] =====
__global__ __launch_bounds__(256, 2) void tc_gemm_main(float* __restrict__ out) {
    extern __shared__ char smem[];
    uint32_t sb = smem_to_u32(smem);
    const int t = threadIdx.x, lane = t & 31, wid = t >> 5;
    const int warp_m = wid & 3, warp_n = wid >> 2;
    const int n0 = blockIdx.x * 128;
    const int m0 = blockIdx.y * 128;
    const int bz = m0 >> 14;

    const __half* A  = g_xf16 + (size_t)m0 * 256;
    const __half* Bh = g_WeffT_h + (size_t)bz * 65536 + (size_t)n0 * 256;
    const __half* Bl = g_WeffT_l + (size_t)bz * 65536 + (size_t)n0 * 256;

    float acc[2][8][4];
#pragma unroll
    for (int i = 0; i < 2; ++i)
#pragma unroll
        for (int j = 0; j < 8; ++j)
#pragma unroll
            for (int k = 0; k < 4; ++k) acc[i][j][k] = 0.0f;

    load_chunk(sb, 0, t, 0, A, Bh, Bl);
    CP_COMMIT();
    for (int c = 0; c < 4; ++c) {
        if (c + 1 < 4) {
            load_chunk(sb, (c + 1) & 1, t, c + 1, A, Bh, Bl);
            CP_COMMIT();
            CP_WAIT(1);
        } else {
            CP_WAIT(0);
        }
        __syncthreads();
        compute_chunk(sb + SA(c & 1), sb + SBH(c & 1), sb + SBL(c & 1),
                      warp_m, warp_n, lane, acc);
        __syncthreads();
    }

    const float* bias = g_beff + (bz << 8);
    const int g = lane >> 2, tt2 = (lane & 3) * 2;
#pragma unroll
    for (int ms = 0; ms < 2; ++ms)
#pragma unroll
        for (int nb8 = 0; nb8 < 8; ++nb8) {
            int m = m0 + warp_m * 32 + ms * 16 + g;
            int n = n0 + warp_n * 64 + nb8 * 8 + tt2;
            float b0 = bias[n], b1 = bias[n + 1];
            float2 v0 = make_float2(acc[ms][nb8][0] + b0, acc[ms][nb8][1] + b1);
            float2 v1 = make_float2(acc[ms][nb8][2] + b0, acc[ms][nb8][3] + b1);
            *(float2*)&out[(size_t)m * 256 + n]       = v0;
            *(float2*)&out[(size_t)(m + 8) * 256 + n] = v1;
        }
}

// ===== block reductions =====
__device__ __forceinline__ float blockSum256(float v, float* red) {
    const int t = threadIdx.x;
#pragma unroll
    for (int o = 16; o > 0; o >>= 1) v += __shfl_xor_sync(0xffffffffu, v, o);
    if ((t & 31) == 0) red[t >> 5] = v;
    __syncthreads();
    if (t < 32) {
        float x = (t < 8) ? red[t] : 0.0f;
#pragma unroll
        for (int o = 4; o > 0; o >>= 1) x += __shfl_xor_sync(0xffffffffu, x, o);
        if (t == 0) red[0] = x;
    }
    __syncthreads();
    float r = red[0];
    __syncthreads();
    return r;
}
__device__ __forceinline__ float blockMax256(float v, float* red) {
    const int t = threadIdx.x;
#pragma unroll
    for (int o = 16; o > 0; o >>= 1) v = fmaxf(v, __shfl_xor_sync(0xffffffffu, v, o));
    if ((t & 31) == 0) red[t >> 5] = v;
    __syncthreads();
    if (t < 32) {
        float x = (t < 8) ? red[t] : -3.402823466e38f;
#pragma unroll
        for (int o = 4; o > 0; o >>= 1) x = fmaxf(x, __shfl_xor_sync(0xffffffffu, x, o));
        if (t == 0) red[0] = x;
    }
    __syncthreads();
    float r = red[0];
    __syncthreads();
    return r;
}

// ===== kernel 4: softmax over l + rolled reduction -> g_s =====
__global__ __launch_bounds__(256) void softmax_reduce() {
    const int bj = blockIdx.x;
    const float* arow = g_xaT + (size_t)bj * 4096;
    const float* brow = g_xbT + (size_t)bj * 4096;
    __shared__ float sE[4096];
    __shared__ float red[32];
    const int t = threadIdx.x;

    float mx = -3.402823466e38f;
#pragma unroll 4
    for (int i = t; i < 1024; i += 256) {
        float4 v = ((const float4*)arow)[i];
        ((float4*)sE)[i] = v;
        mx = fmaxf(mx, fmaxf(fmaxf(v.x, v.y), fmaxf(v.z, v.w)));
    }
    mx = blockMax256(mx, red);

    float sum = 0.0f;
#pragma unroll 4
    for (int i = t; i < 1024; i += 256) {
        float4 v = ((float4*)sE)[i];
        v.x = __expf(v.x - mx); v.y = __expf(v.y - mx);
        v.z = __expf(v.z - mx); v.w = __expf(v.w - mx);
        ((float4*)sE)[i] = v;
        sum += (v.x + v.y) + (v.z + v.w);
    }
    sum = blockSum256(sum, red);
    const float inv = 1.0f / sum;

    const int j = bj & 255;
    const int d = j & 63;
    const int h = j >> 6;

    float accv = 0.0f;
#pragma unroll 4
    for (int l = t; l < 4096; l += 256) {
        const float p = sE[l];
        accv += p * (brow[l] - brow[(l + d) & 4095]);
    }
    accv = blockSum256(accv, red);
    if (t == 0) g_s[(bj & ~255) + d * 4 + h] = accv * inv;
}

// ===== kernel 5: W_eff^T[b] (fp16 split) + beff =====
__global__ __launch_bounds__(256) void build_weff(const float* __restrict__ Wo) {
    const int b  = blockIdx.z;
    const int o0 = blockIdx.x * 64;
    const int i0 = blockIdx.y * 64;
    const float* s = g_s + b * 256;

    __shared__ float As[16][65];
    __shared__ float Bs[16][64];

    const int t  = threadIdx.x;
    const int tx = t & 15;
    const int ty = t >> 4;

    float acc[4][4];
#pragma unroll
    for (int i = 0; i < 4; i++)
#pragma unroll
        for (int j = 0; j < 4; j++) acc[i][j] = 0.0f;

    for (int k0 = 0; k0 < 256; k0 += 16) {
#pragma unroll
        for (int r = 0; r < 4; ++r) {
            int kk = (t >> 6) * 4 + r;
            int irow = t & 63;
            As[kk][irow] = g_WcPT[(size_t)(k0 + kk) * 256 + i0 + irow] * s[k0 + kk];
        }
        *(float4*)&Bs[t >> 4][(t & 15) * 4] =
            *(const float4*)(Wo + (size_t)(k0 + (t >> 4)) * 256 + o0 + (t & 15) * 4);
        __syncthreads();
#pragma unroll
        for (int k = 0; k < 16; k++) {
            float af[4], bf[4];
#pragma unroll
            for (int i = 0; i < 4; i++) af[i] = As[k][ty + 16 * i];
#pragma unroll
            for (int j = 0; j < 4; j++) bf[j] = Bs[k][tx + 16 * j];
#pragma unroll
            for (int i = 0; i < 4; i++)
#pragma unroll
                for (int j = 0; j < 4; j++) acc[i][j] += af[i] * bf[j];
        }
        __syncthreads();
    }

#pragma unroll
    for (int i = 0; i < 4; i++)
#pragma unroll
        for (int j = 0; j < 4; j++) {
            float v = acc[i][j];
            int o = o0 + tx + 16 * j;
            int irow = i0 + ty + 16 * i;
            __half h = __float2half_rn(v);
            __half l = __float2half_rn(v - __half2float(h));
            g_WeffT_h[(size_t)b * 65536 + (size_t)o * 256 + irow] = h;
            g_WeffT_l[(size_t)b * 65536 + (size_t)o * 256 + irow] = l;
        }
}

__global__ void build_beff(const float* __restrict__ bc,
                           const float* __restrict__ Wo,
                           const float* __restrict__ bo) {
    const int b = blockIdx.x;
    const int o = threadIdx.x;
    const float* s = g_s + b * 256;
    float acc = bo[o];
    for (int k = 0; k < 256; k++) {
        const int pc = ((k & 3) << 6) + (k >> 2);
        acc += bc[pc] * s[k] * Wo[(size_t)k * 256 + o];
    }
    g_beff[b * 256 + o] = acc;
}

// ======================= launch =======================
extern "C" void kernel_launch(void* const* d_in, const int* in_sizes, int n_in,
                              void* d_out, int out_size)
{
    const float* x  = (const float*)d_in[0];
    const float* Wa = (const float*)d_in[1];
    const float* ba = (const float*)d_in[2];
    const float* Wb = (const float*)d_in[3];
    const float* bb = (const float*)d_in[4];
    const float* Wc = (const float*)d_in[5];
    const float* bc = (const float*)d_in[6];
    const float* Wo = (const float*)d_in[7];
    const float* bo = (const float*)d_in[8];
    float* out = (float*)d_out;

    cudaFuncSetAttribute(tc_gemm_ab,   cudaFuncAttributeMaxDynamicSharedMemorySize, GEMM_SMEM);
    cudaFuncSetAttribute(tc_gemm_main, cudaFuncAttributeMaxDynamicSharedMemorySize, GEMM_SMEM);

    pool_convert<<<PB * PLS * 64 / 256, 256>>>(x);
    prep_w<<<dim3(8, 8, 3), dim3(32, 8)>>>(Wa, Wb, Wc);
    tc_gemm_ab<<<dim3(4, 256), 256, GEMM_SMEM>>>(ba, bb);
    softmax_reduce<<<PB * PCOUT, 256>>>();
    build_weff<<<dim3(4, 4, PB), 256>>>(Wo);
    build_beff<<<PB, 256>>>(bc, Wo, bo);
    tc_gemm_main<<<dim3(2, 1024), 256, GEMM_SMEM>>>(out);
}

// round 5
// speedup vs baseline: 3.9093x; 1.2692x over previous
#include <cuda_runtime.h>
#include <cuda_fp16.h>
#include <cstdint>

// Problem constants
#define PB    8
#define PL    16384
#define PCIN  256
#define PCOUT 256
#define PS    4
#define PH    4
#define PD    64
#define PLS   4096   // L/S

// ======================= scratch =======================
__device__ __half g_xf16 [PB * PL * PCIN];      // x fp16 (B*L, 256)
__device__ __half g_xpf16[PB * PLS * PCIN];     // pooled fp16 (B*LS, 256)
__device__ __half g_WaT[PCOUT * PCIN];          // [n][k] fp16
__device__ __half g_WbT[PCOUT * PCIN];
__device__ float  g_WcPT[PCOUT * PCIN];         // WcPT[k][i] = Wc[i][perm(k)]
__device__ float  g_xaT [PB * PCOUT * PLS];     // (b, j, l) fp32
__device__ float  g_xbT [PB * PCOUT * PLS];
__device__ float  g_s   [PB * PCOUT];
__device__ __half g_WeffT[PB * PCOUT * PCOUT];  // [b][n][k] fp16
__device__ float  g_beff[PB * PCOUT];

// ======================= PTX helpers (family-portable) =======================
__device__ __forceinline__ uint32_t smem_to_u32(const void* p) {
    uint32_t a;
    asm("{ .reg .u64 t; cvta.to.shared.u64 t, %1; cvt.u32.u64 %0, t; }" : "=r"(a) : "l"(p));
    return a;
}
__device__ __forceinline__ void cp16(uint32_t saddr, const void* g) {
    asm volatile("cp.async.cg.shared.global [%0], [%1], 16;" :: "r"(saddr), "l"(g));
}
#define CP_COMMIT() asm volatile("cp.async.commit_group;" ::: "memory")
#define CP_WAIT(n)  asm volatile("cp.async.wait_group %0;" :: "n"(n) : "memory")

__device__ __forceinline__ void ldm_x4(uint32_t* d, uint32_t addr) {
    asm volatile("ldmatrix.sync.aligned.m8n8.x4.shared.b16 {%0,%1,%2,%3}, [%4];"
        : "=r"(d[0]), "=r"(d[1]), "=r"(d[2]), "=r"(d[3]) : "r"(addr));
}
__device__ __forceinline__ void mma_f16(float* c, const uint32_t* a, const uint32_t* b) {
    asm volatile("mma.sync.aligned.m16n8k16.row.col.f32.f16.f16.f32 "
        "{%0,%1,%2,%3}, {%4,%5,%6,%7}, {%8,%9}, {%0,%1,%2,%3};"
        : "+f"(c[0]), "+f"(c[1]), "+f"(c[2]), "+f"(c[3])
        : "r"(a[0]), "r"(a[1]), "r"(a[2]), "r"(a[3]), "r"(b[0]), "r"(b[1]));
}

// XOR swizzle for 128B rows (8 chunks of 16B)
__device__ __forceinline__ uint32_t swz(int row, int chunk) {
    return (uint32_t)(row * 128 + (((chunk ^ row) & 7) << 4));
}

__device__ __forceinline__ uint2 cvt4h(float4 v) {
    __half2 p0 = __floats2half2_rn(v.x, v.y);
    __half2 p1 = __floats2half2_rn(v.z, v.w);
    uint2 r;
    r.x = *(uint32_t*)&p0; r.y = *(uint32_t*)&p1;
    return r;
}

// ===== kernel 1: pool + fp32 -> fp16 conversion =====
__global__ void pool_convert(const float* __restrict__ x) {
    int idx = blockIdx.x * blockDim.x + threadIdx.x;   // B*LS*64
    if (idx >= PB * PLS * 64) return;
    int rowp = idx >> 6, c4 = idx & 63;
    const float4* px = (const float4*)x + (size_t)rowp * 256 + c4;
    uint2* xf = (uint2*)g_xf16;
    float4 v[4];
#pragma unroll
    for (int s = 0; s < 4; ++s) {
        v[s] = px[(size_t)s * 64];
        xf[(size_t)(rowp * 4 + s) * 64 + c4] = cvt4h(v[s]);
    }
    float4 r;
    r.x = fmaxf(fmaxf(v[0].x, v[1].x), fmaxf(v[2].x, v[3].x));
    r.y = fmaxf(fmaxf(v[0].y, v[1].y), fmaxf(v[2].y, v[3].y));
    r.z = fmaxf(fmaxf(v[0].z, v[1].z), fmaxf(v[2].z, v[3].z));
    r.w = fmaxf(fmaxf(v[0].w, v[1].w), fmaxf(v[2].w, v[3].w));
    ((uint2*)g_xpf16)[(size_t)rowp * 64 + c4] = cvt4h(r);
}

// ===== kernel 2: weight prep (transpose + fp16; Wc permute-transpose) =====
__global__ void prep_w(const float* __restrict__ Wa, const float* __restrict__ Wb,
                       const float* __restrict__ Wc) {
    __shared__ float tile[32][33];
    const int zm = blockIdx.z;
    const int j0 = blockIdx.x * 32, i0 = blockIdx.y * 32;
    const float* src = (zm == 0) ? Wa : (zm == 1) ? Wb : Wc;
    for (int r = threadIdx.y; r < 32; r += 8)
        tile[r][threadIdx.x] = src[(size_t)(i0 + r) * 256 + j0 + threadIdx.x];
    __syncthreads();
    for (int r = threadIdx.y; r < 32; r += 8) {
        int j = j0 + r;
        float val = tile[threadIdx.x][r];           // = src[i0+tx][j]
        int i = i0 + threadIdx.x;
        if (zm == 2) {
            int k = ((j & 63) << 2) | (j >> 6);     // inverse of perm
            g_WcPT[(size_t)k * 256 + i] = val;
        } else {
            __half h = __float2half_rn(val);
            if (zm == 0) g_WaT[(size_t)j * 256 + i] = h;
            else         g_WbT[(size_t)j * 256 + i] = h;
        }
    }
}

// ======================= HMMA GEMM core =======================
// CTA: 128(M) x 128(N); K=256 in 4 chunks of 64. Pure fp16 x fp16, fp32 accum.
// SMEM tiles: 128 rows x 128B, XOR-swizzled -> 16 KB each; {A,B} x2 buffers = 64 KB.
#define SA(buf) ((buf) * 32768 + 0)
#define SB(buf) ((buf) * 32768 + 16384)
#define GEMM_SMEM_MAIN 65536
#define GEMM_SMEM_AB   66048   // epilogue staging needs 128*129*4

__device__ __forceinline__ void load_tile(uint32_t s, int t, const __half* g) {
#pragma unroll
    for (int i = 0; i < 4; ++i) {
        int lin = i * 256 + t;
        int r = lin >> 3, ch = lin & 7;
        cp16(s + swz(r, ch), g + (size_t)r * 256 + ch * 8);
    }
}

__device__ __forceinline__ void load_chunk(uint32_t sb, int buf, int c,
    int t, const __half* A, const __half* B) {
    load_tile(sb + SA(buf), t, A + c * 64);
    load_tile(sb + SB(buf), t, B + c * 64);
}

__device__ __forceinline__ void compute_chunk(uint32_t sA, uint32_t sB,
    int warp_m, int warp_n, int lane, float acc[2][8][4])
{
    const int lrow = lane & 15;
    const int ach  = lane >> 4;
    const int nrow = (lane & 7) | ((lane >> 4) << 3);
    const int bch  = (lane >> 3) & 1;
#pragma unroll
    for (int ks = 0; ks < 4; ++ks) {
        uint32_t a[2][4];
        ldm_x4(a[0], sA + swz(warp_m * 32 +      lrow, ks * 2 + ach));
        ldm_x4(a[1], sA + swz(warp_m * 32 + 16 + lrow, ks * 2 + ach));
        uint32_t b[4][4];
#pragma unroll
        for (int nb = 0; nb < 4; ++nb)
            ldm_x4(b[nb], sB + swz(warp_n * 64 + nb * 16 + nrow, ks * 2 + bch));
#pragma unroll
        for (int ms = 0; ms < 2; ++ms)
#pragma unroll
            for (int nb = 0; nb < 4; ++nb) {
                mma_f16(acc[ms][nb * 2 + 0], a[ms], &b[nb][0]);
                mma_f16(acc[ms][nb * 2 + 1], a[ms], &b[nb][2]);
            }
    }
}

// ===== kernel 3: x_a/x_b GEMM with transposed fp32 store =====
__global__ __launch_bounds__(256, 2) void tc_gemm_ab(const float* __restrict__ ba,
                                                     const float* __restrict__ bb) {
    extern __shared__ char smem[];
    uint32_t sb = smem_to_u32(smem);
    const int t = threadIdx.x, lane = t & 31, wid = t >> 5;
    const int warp_m = wid & 3, warp_n = wid >> 2;
    const int which = blockIdx.x >> 1;
    const int n0 = (blockIdx.x & 1) * 128;
    const int m0 = blockIdx.y * 128;

    const __half* A = g_xpf16 + (size_t)m0 * 256;
    const __half* B = (which ? g_WbT : g_WaT) + (size_t)n0 * 256;

    float acc[2][8][4];
#pragma unroll
    for (int i = 0; i < 2; ++i)
#pragma unroll
        for (int j = 0; j < 8; ++j)
#pragma unroll
            for (int k = 0; k < 4; ++k) acc[i][j][k] = 0.0f;

    load_chunk(sb, 0, 0, t, A, B);
    CP_COMMIT();
    for (int c = 0; c < 4; ++c) {
        if (c + 1 < 4) {
            load_chunk(sb, (c + 1) & 1, c + 1, t, A, B);
            CP_COMMIT();
            CP_WAIT(1);
        } else {
            CP_WAIT(0);
        }
        __syncthreads();
        compute_chunk(sb + SA(c & 1), sb + SB(c & 1), warp_m, warp_n, lane, acc);
        __syncthreads();
    }

    // stage C in smem, then coalesced transposed store
    float* Cs = (float*)smem;                       // [128][129]
    const int g = lane >> 2, tt2 = (lane & 3) * 2;
#pragma unroll
    for (int ms = 0; ms < 2; ++ms)
#pragma unroll
        for (int nb8 = 0; nb8 < 8; ++nb8) {
            int ml = warp_m * 32 + ms * 16 + g;
            int nl = warp_n * 64 + nb8 * 8 + tt2;
            Cs[ml * 129 + nl]           = acc[ms][nb8][0];
            Cs[ml * 129 + nl + 1]       = acc[ms][nb8][1];
            Cs[(ml + 8) * 129 + nl]     = acc[ms][nb8][2];
            Cs[(ml + 8) * 129 + nl + 1] = acc[ms][nb8][3];
        }
    __syncthreads();

    const int b = m0 >> 12, l0 = m0 & 4095;
    float* outT = which ? g_xbT : g_xaT;
    const float* bias = which ? bb : ba;
    for (int i = 0; i < 64; ++i) {
        int lin = i * 256 + t;
        int n = lin >> 7, l = lin & 127;
        outT[(size_t)((b << 8) + n0 + n) * 4096 + l0 + l] = Cs[l * 129 + n] + bias[n0 + n];
    }
}

// ===== kernel 6: main GEMM out = x @ Weff[b] + beff[b] =====
__global__ __launch_bounds__(256, 2) void tc_gemm_main(float* __restrict__ out) {
    extern __shared__ char smem[];
    uint32_t sb = smem_to_u32(smem);
    const int t = threadIdx.x, lane = t & 31, wid = t >> 5;
    const int warp_m = wid & 3, warp_n = wid >> 2;
    const int n0 = blockIdx.x * 128;
    const int m0 = blockIdx.y * 128;
    const int bz = m0 >> 14;

    const __half* A = g_xf16 + (size_t)m0 * 256;
    const __half* B = g_WeffT + (size_t)bz * 65536 + (size_t)n0 * 256;

    float acc[2][8][4];
#pragma unroll
    for (int i = 0; i < 2; ++i)
#pragma unroll
        for (int j = 0; j < 8; ++j)
#pragma unroll
            for (int k = 0; k < 4; ++k) acc[i][j][k] = 0.0f;

    load_chunk(sb, 0, 0, t, A, B);
    CP_COMMIT();
    for (int c = 0; c < 4; ++c) {
        if (c + 1 < 4) {
            load_chunk(sb, (c + 1) & 1, c + 1, t, A, B);
            CP_COMMIT();
            CP_WAIT(1);
        } else {
            CP_WAIT(0);
        }
        __syncthreads();
        compute_chunk(sb + SA(c & 1), sb + SB(c & 1), warp_m, warp_n, lane, acc);
        __syncthreads();
    }

    const float* bias = g_beff + (bz << 8);
    const int g = lane >> 2, tt2 = (lane & 3) * 2;
#pragma unroll
    for (int ms = 0; ms < 2; ++ms)
#pragma unroll
        for (int nb8 = 0; nb8 < 8; ++nb8) {
            int m = m0 + warp_m * 32 + ms * 16 + g;
            int n = n0 + warp_n * 64 + nb8 * 8 + tt2;
            float b0 = bias[n], b1 = bias[n + 1];
            float2 v0 = make_float2(acc[ms][nb8][0] + b0, acc[ms][nb8][1] + b1);
            float2 v1 = make_float2(acc[ms][nb8][2] + b0, acc[ms][nb8][3] + b1);
            *(float2*)&out[(size_t)m * 256 + n]       = v0;
            *(float2*)&out[(size_t)(m + 8) * 256 + n] = v1;
        }
}

// ===== block reductions =====
__device__ __forceinline__ float blockSum256(float v, float* red) {
    const int t = threadIdx.x;
#pragma unroll
    for (int o = 16; o > 0; o >>= 1) v += __shfl_xor_sync(0xffffffffu, v, o);
    if ((t & 31) == 0) red[t >> 5] = v;
    __syncthreads();
    if (t < 32) {
        float x = (t < 8) ? red[t] : 0.0f;
#pragma unroll
        for (int o = 4; o > 0; o >>= 1) x += __shfl_xor_sync(0xffffffffu, x, o);
        if (t == 0) red[0] = x;
    }
    __syncthreads();
    float r = red[0];
    __syncthreads();
    return r;
}
__device__ __forceinline__ float blockMax256(float v, float* red) {
    const int t = threadIdx.x;
#pragma unroll
    for (int o = 16; o > 0; o >>= 1) v = fmaxf(v, __shfl_xor_sync(0xffffffffu, v, o));
    if ((t & 31) == 0) red[t >> 5] = v;
    __syncthreads();
    if (t < 32) {
        float x = (t < 8) ? red[t] : -3.402823466e38f;
#pragma unroll
        for (int o = 4; o > 0; o >>= 1) x = fmaxf(x, __shfl_xor_sync(0xffffffffu, x, o));
        if (t == 0) red[0] = x;
    }
    __syncthreads();
    float r = red[0];
    __syncthreads();
    return r;
}

// ===== kernel 4: softmax over l + rolled reduction -> g_s =====
__global__ __launch_bounds__(256) void softmax_reduce() {
    const int bj = blockIdx.x;
    const float* arow = g_xaT + (size_t)bj * 4096;
    const float* brow = g_xbT + (size_t)bj * 4096;
    __shared__ float sE[4096];
    __shared__ float red[32];
    const int t = threadIdx.x;

    float mx = -3.402823466e38f;
#pragma unroll 4
    for (int i = t; i < 1024; i += 256) {
        float4 v = ((const float4*)arow)[i];
        ((float4*)sE)[i] = v;
        mx = fmaxf(mx, fmaxf(fmaxf(v.x, v.y), fmaxf(v.z, v.w)));
    }
    mx = blockMax256(mx, red);

    float sum = 0.0f;
#pragma unroll 4
    for (int i = t; i < 1024; i += 256) {
        float4 v = ((float4*)sE)[i];
        v.x = __expf(v.x - mx); v.y = __expf(v.y - mx);
        v.z = __expf(v.z - mx); v.w = __expf(v.w - mx);
        ((float4*)sE)[i] = v;
        sum += (v.x + v.y) + (v.z + v.w);
    }
    sum = blockSum256(sum, red);
    const float inv = 1.0f / sum;

    const int j = bj & 255;
    const int d = j & 63;
    const int h = j >> 6;

    float accv = 0.0f;
#pragma unroll 4
    for (int l = t; l < 4096; l += 256) {
        const float p = sE[l];
        accv += p * (brow[l] - brow[(l + d) & 4095]);
    }
    accv = blockSum256(accv, red);
    if (t == 0) g_s[(bj & ~255) + d * 4 + h] = accv * inv;
}

// ===== kernel 5: W_eff^T[b] (fp16) + beff =====
__global__ __launch_bounds__(256) void build_weff(const float* __restrict__ Wo) {
    const int b  = blockIdx.z;
    const int o0 = blockIdx.x * 64;
    const int i0 = blockIdx.y * 64;
    const float* s = g_s + b * 256;

    __shared__ float As[16][65];
    __shared__ float Bs[16][64];

    const int t  = threadIdx.x;
    const int tx = t & 15;
    const int ty = t >> 4;

    float acc[4][4];
#pragma unroll
    for (int i = 0; i < 4; i++)
#pragma unroll
        for (int j = 0; j < 4; j++) acc[i][j] = 0.0f;

    for (int k0 = 0; k0 < 256; k0 += 16) {
#pragma unroll
        for (int r = 0; r < 4; ++r) {
            int kk = (t >> 6) * 4 + r;
            int irow = t & 63;
            As[kk][irow] = g_WcPT[(size_t)(k0 + kk) * 256 + i0 + irow] * s[k0 + kk];
        }
        *(float4*)&Bs[t >> 4][(t & 15) * 4] =
            *(const float4*)(Wo + (size_t)(k0 + (t >> 4)) * 256 + o0 + (t & 15) * 4);
        __syncthreads();
#pragma unroll
        for (int k = 0; k < 16; k++) {
            float af[4], bf[4];
#pragma unroll
            for (int i = 0; i < 4; i++) af[i] = As[k][ty + 16 * i];
#pragma unroll
            for (int j = 0; j < 4; j++) bf[j] = Bs[k][tx + 16 * j];
#pragma unroll
            for (int i = 0; i < 4; i++)
#pragma unroll
                for (int j = 0; j < 4; j++) acc[i][j] += af[i] * bf[j];
        }
        __syncthreads();
    }

#pragma unroll
    for (int i = 0; i < 4; i++)
#pragma unroll
        for (int j = 0; j < 4; j++) {
            int o = o0 + tx + 16 * j;
            int irow = i0 + ty + 16 * i;
            g_WeffT[(size_t)b * 65536 + (size_t)o * 256 + irow] = __float2half_rn(acc[i][j]);
        }
}

__global__ void build_beff(const float* __restrict__ bc,
                           const float* __restrict__ Wo,
                           const float* __restrict__ bo) {
    const int b = blockIdx.x;
    const int o = threadIdx.x;
    const float* s = g_s + b * 256;
    float acc = bo[o];
    for (int k = 0; k < 256; k++) {
        const int pc = ((k & 3) << 6) + (k >> 2);
        acc += bc[pc] * s[k] * Wo[(size_t)k * 256 + o];
    }
    g_beff[b * 256 + o] = acc;
}

// ======================= launch =======================
extern "C" void kernel_launch(void* const* d_in, const int* in_sizes, int n_in,
                              void* d_out, int out_size)
{
    const float* x  = (const float*)d_in[0];
    const float* Wa = (const float*)d_in[1];
    const float* ba = (const float*)d_in[2];
    const float* Wb = (const float*)d_in[3];
    const float* bb = (const float*)d_in[4];
    const float* Wc = (const float*)d_in[5];
    const float* bc = (const float*)d_in[6];
    const float* Wo = (const float*)d_in[7];
    const float* bo = (const float*)d_in[8];
    float* out = (float*)d_out;

    cudaFuncSetAttribute(tc_gemm_ab,   cudaFuncAttributeMaxDynamicSharedMemorySize, GEMM_SMEM_AB);
    cudaFuncSetAttribute(tc_gemm_main, cudaFuncAttributeMaxDynamicSharedMemorySize, GEMM_SMEM_MAIN);

    pool_convert<<<PB * PLS * 64 / 256, 256>>>(x);
    prep_w<<<dim3(8, 8, 3), dim3(32, 8)>>>(Wa, Wb, Wc);
    tc_gemm_ab<<<dim3(4, 256), 256, GEMM_SMEM_AB>>>(ba, bb);
    softmax_reduce<<<PB * PCOUT, 256>>>();
    build_weff<<<dim3(4, 4, PB), 256>>>(Wo);
    build_beff<<<PB, 256>>>(bc, Wo, bo);
    tc_gemm_main<<<dim3(2, 1024), 256, GEMM_SMEM_MAIN>>>(out);
}

// round 6
// speedup vs baseline: 3.9964x; 1.0223x over previous
#include <cuda_runtime.h>
#include <cuda_fp16.h>
#include <cstdint>

// Problem constants
#define PB    8
#define PL    16384
#define PCIN  256
#define PCOUT 256
#define PS    4
#define PH    4
#define PD    64
#define PLS   4096   // L/S

// ======================= scratch =======================
__device__ __half g_xf16 [PB * PL * PCIN];      // x fp16 (B*L, 256)
__device__ __half g_xpf16[PB * PLS * PCIN];     // pooled fp16 (B*LS, 256)
__device__ __half g_WaT[PCOUT * PCIN];          // [n][k] fp16
__device__ __half g_WbT[PCOUT * PCIN];
__device__ float  g_WcPT[PCOUT * PCIN];         // WcPT[k][i] = Wc[i][perm(k)]
__device__ float  g_xaT [PB * PCOUT * PLS];     // (b, j, l) fp32  (softmax logits)
__device__ __half g_xbTh[PB * PCOUT * PLS];     // (b, j, l) fp16  (linear term)
__device__ float  g_s   [PB * PCOUT];
__device__ __half g_WeffT[PB * PCOUT * PCOUT];  // [b][n][k] fp16
__device__ float  g_beff[PB * PCOUT];

// ======================= PTX helpers (family-portable) =======================
__device__ __forceinline__ uint32_t smem_to_u32(const void* p) {
    uint32_t a;
    asm("{ .reg .u64 t; cvta.to.shared.u64 t, %1; cvt.u32.u64 %0, t; }" : "=r"(a) : "l"(p));
    return a;
}
__device__ __forceinline__ void cp16(uint32_t saddr, const void* g) {
    asm volatile("cp.async.cg.shared.global [%0], [%1], 16;" :: "r"(saddr), "l"(g));
}
#define CP_COMMIT() asm volatile("cp.async.commit_group;" ::: "memory")
#define CP_WAIT(n)  asm volatile("cp.async.wait_group %0;" :: "n"(n) : "memory")

__device__ __forceinline__ void ldm_x4(uint32_t* d, uint32_t addr) {
    asm volatile("ldmatrix.sync.aligned.m8n8.x4.shared.b16 {%0,%1,%2,%3}, [%4];"
        : "=r"(d[0]), "=r"(d[1]), "=r"(d[2]), "=r"(d[3]) : "r"(addr));
}
__device__ __forceinline__ void mma_f16(float* c, const uint32_t* a, const uint32_t* b) {
    asm volatile("mma.sync.aligned.m16n8k16.row.col.f32.f16.f16.f32 "
        "{%0,%1,%2,%3}, {%4,%5,%6,%7}, {%8,%9}, {%0,%1,%2,%3};"
        : "+f"(c[0]), "+f"(c[1]), "+f"(c[2]), "+f"(c[3])
        : "r"(a[0]), "r"(a[1]), "r"(a[2]), "r"(a[3]), "r"(b[0]), "r"(b[1]));
}

// swizzles: A tiles have 128B rows (8 chunks of 16B), B tile has 512B rows (32 chunks)
__device__ __forceinline__ uint32_t swzA(int row, int ch) {
    return (uint32_t)(row * 128 + (((ch ^ row) & 7) << 4));
}
__device__ __forceinline__ uint32_t swzB(int row, int ch) {
    return (uint32_t)(row * 512 + ((ch & 24) << 4) + (((ch ^ row) & 7) << 4));
}

__device__ __forceinline__ uint2 cvt4h(float4 v) {
    __half2 p0 = __floats2half2_rn(v.x, v.y);
    __half2 p1 = __floats2half2_rn(v.z, v.w);
    uint2 r;
    r.x = *(uint32_t*)&p0; r.y = *(uint32_t*)&p1;
    return r;
}

// ===== kernel 1: pool + fp32 -> fp16 conversion =====
__global__ void pool_convert(const float* __restrict__ x) {
    int idx = blockIdx.x * blockDim.x + threadIdx.x;   // B*LS*64
    if (idx >= PB * PLS * 64) return;
    int rowp = idx >> 6, c4 = idx & 63;
    const float4* px = (const float4*)x + (size_t)rowp * 256 + c4;
    uint2* xf = (uint2*)g_xf16;
    float4 v[4];
#pragma unroll
    for (int s = 0; s < 4; ++s) {
        v[s] = px[(size_t)s * 64];
        xf[(size_t)(rowp * 4 + s) * 64 + c4] = cvt4h(v[s]);
    }
    float4 r;
    r.x = fmaxf(fmaxf(v[0].x, v[1].x), fmaxf(v[2].x, v[3].x));
    r.y = fmaxf(fmaxf(v[0].y, v[1].y), fmaxf(v[2].y, v[3].y));
    r.z = fmaxf(fmaxf(v[0].z, v[1].z), fmaxf(v[2].z, v[3].z));
    r.w = fmaxf(fmaxf(v[0].w, v[1].w), fmaxf(v[2].w, v[3].w));
    ((uint2*)g_xpf16)[(size_t)rowp * 64 + c4] = cvt4h(r);
}

// ===== kernel 2: weight prep (transpose + fp16; Wc permute-transpose) =====
__global__ void prep_w(const float* __restrict__ Wa, const float* __restrict__ Wb,
                       const float* __restrict__ Wc) {
    __shared__ float tile[32][33];
    const int zm = blockIdx.z;
    const int j0 = blockIdx.x * 32, i0 = blockIdx.y * 32;
    const float* src = (zm == 0) ? Wa : (zm == 1) ? Wb : Wc;
    for (int r = threadIdx.y; r < 32; r += 8)
        tile[r][threadIdx.x] = src[(size_t)(i0 + r) * 256 + j0 + threadIdx.x];
    __syncthreads();
    for (int r = threadIdx.y; r < 32; r += 8) {
        int j = j0 + r;
        float val = tile[threadIdx.x][r];           // = src[i0+tx][j]
        int i = i0 + threadIdx.x;
        if (zm == 2) {
            int k = ((j & 63) << 2) | (j >> 6);     // inverse of perm
            g_WcPT[(size_t)k * 256 + i] = val;
        } else {
            __half h = __float2half_rn(val);
            if (zm == 0) g_WaT[(size_t)j * 256 + i] = h;
            else         g_WbT[(size_t)j * 256 + i] = h;
        }
    }
}

// ======================= HMMA GEMM core =======================
// CTA: 128(M) x 128(N); K=256. B tile resident (64 KB, 512B rows);
// A chunks of 128x64 (16 KB, 128B rows), triple-buffered, 1-ahead cp.async.
#define SBB 0
#define SAB(buf) (65536 + (buf) * 16384)
#define GEMM_SMEM 114688

__device__ __forceinline__ void load_tileA(uint32_t s, int t, const __half* g) {
#pragma unroll
    for (int i = 0; i < 4; ++i) {
        int lin = i * 256 + t;
        int r = lin >> 3, ch = lin & 7;
        cp16(s + swzA(r, ch), g + (size_t)r * 256 + ch * 8);
    }
}
__device__ __forceinline__ void load_B(uint32_t s, int t, const __half* g) {
#pragma unroll
    for (int i = 0; i < 16; ++i) {
        int lin = i * 256 + t;
        int r = lin >> 5, ch = lin & 31;
        cp16(s + swzB(r, ch), g + (size_t)r * 256 + ch * 8);
    }
}

__device__ __forceinline__ void compute_chunk(uint32_t sA, uint32_t sB, int c,
    int warp_m, int warp_n, int lane, float acc[2][8][4])
{
    const int lrow = lane & 15;
    const int ach  = lane >> 4;
    const int nrow = (lane & 7) | ((lane >> 4) << 3);
    const int bch  = (lane >> 3) & 1;
#pragma unroll
    for (int ks = 0; ks < 4; ++ks) {
        uint32_t a[2][4];
        ldm_x4(a[0], sA + swzA(warp_m * 32 +      lrow, ks * 2 + ach));
        ldm_x4(a[1], sA + swzA(warp_m * 32 + 16 + lrow, ks * 2 + ach));
        uint32_t b[4][4];
        const int kk = c * 8 + ks * 2 + bch;
#pragma unroll
        for (int nb = 0; nb < 4; ++nb)
            ldm_x4(b[nb], sB + swzB(warp_n * 64 + nb * 16 + nrow, kk));
#pragma unroll
        for (int ms = 0; ms < 2; ++ms)
#pragma unroll
            for (int nb = 0; nb < 4; ++nb) {
                mma_f16(acc[ms][nb * 2 + 0], a[ms], &b[nb][0]);
                mma_f16(acc[ms][nb * 2 + 1], a[ms], &b[nb][2]);
            }
    }
}

// Shared mainloop: returns with acc filled. 4 syncthreads total.
__device__ __forceinline__ void gemm_loop(uint32_t sb, int t, int warp_m, int warp_n,
    int lane, const __half* A, const __half* Bg, float acc[2][8][4])
{
    load_B(sb + SBB, t, Bg);
    load_tileA(sb + SAB(0), t, A);
    CP_COMMIT();
    for (int c = 0; c < 4; ++c) {
        if (c + 1 < 4) {
            load_tileA(sb + SAB((c + 1) % 3), t, A + (c + 1) * 64);
            CP_COMMIT();
            CP_WAIT(1);
        } else {
            CP_WAIT(0);
        }
        __syncthreads();
        compute_chunk(sb + SAB(c % 3), sb + SBB, c, warp_m, warp_n, lane, acc);
    }
}

// ===== kernel 3: x_a/x_b GEMM; x_a -> fp32 transposed, x_b -> fp16 transposed =====
__global__ __launch_bounds__(256, 2) void tc_gemm_ab(const float* __restrict__ ba,
                                                     const float* __restrict__ bb) {
    extern __shared__ char smem[];
    uint32_t sb = smem_to_u32(smem);
    const int t = threadIdx.x, lane = t & 31, wid = t >> 5;
    const int warp_m = wid & 3, warp_n = wid >> 2;
    const int which = blockIdx.x >> 1;
    const int n0 = (blockIdx.x & 1) * 128;
    const int m0 = blockIdx.y * 128;

    const __half* A  = g_xpf16 + (size_t)m0 * 256;
    const __half* Bg = (which ? g_WbT : g_WaT) + (size_t)n0 * 256;

    float acc[2][8][4];
#pragma unroll
    for (int i = 0; i < 2; ++i)
#pragma unroll
        for (int j = 0; j < 8; ++j)
#pragma unroll
            for (int k = 0; k < 4; ++k) acc[i][j][k] = 0.0f;

    gemm_loop(sb, t, warp_m, warp_n, lane, A, Bg, acc);
    __syncthreads();   // all warps done with SMEM tiles before reuse as Cs

    // stage C in smem, then coalesced transposed store
    float* Cs = (float*)smem;                       // [128][129]
    const int g = lane >> 2, tt2 = (lane & 3) * 2;
#pragma unroll
    for (int ms = 0; ms < 2; ++ms)
#pragma unroll
        for (int nb8 = 0; nb8 < 8; ++nb8) {
            int ml = warp_m * 32 + ms * 16 + g;
            int nl = warp_n * 64 + nb8 * 8 + tt2;
            Cs[ml * 129 + nl]           = acc[ms][nb8][0];
            Cs[ml * 129 + nl + 1]       = acc[ms][nb8][1];
            Cs[(ml + 8) * 129 + nl]     = acc[ms][nb8][2];
            Cs[(ml + 8) * 129 + nl + 1] = acc[ms][nb8][3];
        }
    __syncthreads();

    const int b = m0 >> 12, l0 = m0 & 4095;
    if (which == 0) {
        const float* bias = ba;
        for (int i = 0; i < 64; ++i) {
            int lin = i * 256 + t;
            int n = lin >> 7, l = lin & 127;
            g_xaT[(size_t)((b << 8) + n0 + n) * 4096 + l0 + l] = Cs[l * 129 + n] + bias[n0 + n];
        }
    } else {
        const float* bias = bb;
        for (int i = 0; i < 64; ++i) {
            int lin = i * 256 + t;
            int n = lin >> 7, l = lin & 127;
            g_xbTh[(size_t)((b << 8) + n0 + n) * 4096 + l0 + l] =
                __float2half_rn(Cs[l * 129 + n] + bias[n0 + n]);
        }
    }
}

// ===== kernel 6: main GEMM out = x @ Weff[b] + beff[b] =====
__global__ __launch_bounds__(256, 2) void tc_gemm_main(float* __restrict__ out) {
    extern __shared__ char smem[];
    uint32_t sb = smem_to_u32(smem);
    const int t = threadIdx.x, lane = t & 31, wid = t >> 5;
    const int warp_m = wid & 3, warp_n = wid >> 2;
    const int n0 = blockIdx.x * 128;
    const int m0 = blockIdx.y * 128;
    const int bz = m0 >> 14;

    const __half* A  = g_xf16 + (size_t)m0 * 256;
    const __half* Bg = g_WeffT + (size_t)bz * 65536 + (size_t)n0 * 256;

    float acc[2][8][4];
#pragma unroll
    for (int i = 0; i < 2; ++i)
#pragma unroll
        for (int j = 0; j < 8; ++j)
#pragma unroll
            for (int k = 0; k < 4; ++k) acc[i][j][k] = 0.0f;

    gemm_loop(sb, t, warp_m, warp_n, lane, A, Bg, acc);

    const float* bias = g_beff + (bz << 8);
    const int g = lane >> 2, tt2 = (lane & 3) * 2;
#pragma unroll
    for (int ms = 0; ms < 2; ++ms)
#pragma unroll
        for (int nb8 = 0; nb8 < 8; ++nb8) {
            int m = m0 + warp_m * 32 + ms * 16 + g;
            int n = n0 + warp_n * 64 + nb8 * 8 + tt2;
            float b0 = bias[n], b1 = bias[n + 1];
            float2 v0 = make_float2(acc[ms][nb8][0] + b0, acc[ms][nb8][1] + b1);
            float2 v1 = make_float2(acc[ms][nb8][2] + b0, acc[ms][nb8][3] + b1);
            *(float2*)&out[(size_t)m * 256 + n]       = v0;
            *(float2*)&out[(size_t)(m + 8) * 256 + n] = v1;
        }
}

// ===== block reductions =====
__device__ __forceinline__ float blockSum256(float v, float* red) {
    const int t = threadIdx.x;
#pragma unroll
    for (int o = 16; o > 0; o >>= 1) v += __shfl_xor_sync(0xffffffffu, v, o);
    if ((t & 31) == 0) red[t >> 5] = v;
    __syncthreads();
    if (t < 32) {
        float x = (t < 8) ? red[t] : 0.0f;
#pragma unroll
        for (int o = 4; o > 0; o >>= 1) x += __shfl_xor_sync(0xffffffffu, x, o);
        if (t == 0) red[0] = x;
    }
    __syncthreads();
    float r = red[0];
    __syncthreads();
    return r;
}
__device__ __forceinline__ float blockMax256(float v, float* red) {
    const int t = threadIdx.x;
#pragma unroll
    for (int o = 16; o > 0; o >>= 1) v = fmaxf(v, __shfl_xor_sync(0xffffffffu, v, o));
    if ((t & 31) == 0) red[t >> 5] = v;
    __syncthreads();
    if (t < 32) {
        float x = (t < 8) ? red[t] : -3.402823466e38f;
#pragma unroll
        for (int o = 4; o > 0; o >>= 1) x = fmaxf(x, __shfl_xor_sync(0xffffffffu, x, o));
        if (t == 0) red[0] = x;
    }
    __syncthreads();
    float r = red[0];
    __syncthreads();
    return r;
}

// ===== kernel 4: softmax over l + rolled reduction -> g_s =====
__global__ __launch_bounds__(256) void softmax_reduce() {
    const int bj = blockIdx.x;
    const float* arow  = g_xaT  + (size_t)bj * 4096;
    const __half* browh = g_xbTh + (size_t)bj * 4096;
    __shared__ float sE[4096];
    __shared__ float sB[4096];
    __shared__ float red[32];
    const int t = threadIdx.x;

    float mx = -3.402823466e38f;
#pragma unroll 4
    for (int i = t; i < 1024; i += 256) {
        float4 v = ((const float4*)arow)[i];
        ((float4*)sE)[i] = v;
        mx = fmaxf(mx, fmaxf(fmaxf(v.x, v.y), fmaxf(v.z, v.w)));
        uint2 hv = ((const uint2*)browh)[i];
        __half2 h0 = *(__half2*)&hv.x, h1 = *(__half2*)&hv.y;
        float2 f0 = __half22float2(h0), f1 = __half22float2(h1);
        float4 bvv = make_float4(f0.x, f0.y, f1.x, f1.y);
        ((float4*)sB)[i] = bvv;
    }
    mx = blockMax256(mx, red);

    float sum = 0.0f;
#pragma unroll 4
    for (int i = t; i < 1024; i += 256) {
        float4 v = ((float4*)sE)[i];
        v.x = __expf(v.x - mx); v.y = __expf(v.y - mx);
        v.z = __expf(v.z - mx); v.w = __expf(v.w - mx);
        ((float4*)sE)[i] = v;
        sum += (v.x + v.y) + (v.z + v.w);
    }
    sum = blockSum256(sum, red);
    const float inv = 1.0f / sum;

    const int j = bj & 255;
    const int d = j & 63;
    const int h = j >> 6;

    float accv = 0.0f;
#pragma unroll 4
    for (int l = t; l < 4096; l += 256) {
        accv += sE[l] * (sB[l] - sB[(l + d) & 4095]);
    }
    accv = blockSum256(accv, red);
    if (t == 0) g_s[(bj & ~255) + d * 4 + h] = accv * inv;
}

// ===== kernel 5: W_eff^T[b] (fp16) + beff =====
__global__ __launch_bounds__(256) void build_weff(const float* __restrict__ Wo) {
    const int b  = blockIdx.z;
    const int o0 = blockIdx.x * 64;
    const int i0 = blockIdx.y * 64;
    const float* s = g_s + b * 256;

    __shared__ float As[16][65];
    __shared__ float Bs[16][64];

    const int t  = threadIdx.x;
    const int tx = t & 15;
    const int ty = t >> 4;

    float acc[4][4];
#pragma unroll
    for (int i = 0; i < 4; i++)
#pragma unroll
        for (int j = 0; j < 4; j++) acc[i][j] = 0.0f;

    for (int k0 = 0; k0 < 256; k0 += 16) {
#pragma unroll
        for (int r = 0; r < 4; ++r) {
            int kk = (t >> 6) * 4 + r;
            int irow = t & 63;
            As[kk][irow] = g_WcPT[(size_t)(k0 + kk) * 256 + i0 + irow] * s[k0 + kk];
        }
        *(float4*)&Bs[t >> 4][(t & 15) * 4] =
            *(const float4*)(Wo + (size_t)(k0 + (t >> 4)) * 256 + o0 + (t & 15) * 4);
        __syncthreads();
#pragma unroll
        for (int k = 0; k < 16; k++) {
            float af[4], bf[4];
#pragma unroll
            for (int i = 0; i < 4; i++) af[i] = As[k][ty + 16 * i];
#pragma unroll
            for (int j = 0; j < 4; j++) bf[j] = Bs[k][tx + 16 * j];
#pragma unroll
            for (int i = 0; i < 4; i++)
#pragma unroll
                for (int j = 0; j < 4; j++) acc[i][j] += af[i] * bf[j];
        }
        __syncthreads();
    }

#pragma unroll
    for (int i = 0; i < 4; i++)
#pragma unroll
        for (int j = 0; j < 4; j++) {
            int o = o0 + tx + 16 * j;
            int irow = i0 + ty + 16 * i;
            g_WeffT[(size_t)b * 65536 + (size_t)o * 256 + irow] = __float2half_rn(acc[i][j]);
        }
}

__global__ void build_beff(const float* __restrict__ bc,
                           const float* __restrict__ Wo,
                           const float* __restrict__ bo) {
    const int b = blockIdx.x;
    const int o = threadIdx.x;
    const float* s = g_s + b * 256;
    float acc = bo[o];
    for (int k = 0; k < 256; k++) {
        const int pc = ((k & 3) << 6) + (k >> 2);
        acc += bc[pc] * s[k] * Wo[(size_t)k * 256 + o];
    }
    g_beff[b * 256 + o] = acc;
}

// ======================= launch =======================
extern "C" void kernel_launch(void* const* d_in, const int* in_sizes, int n_in,
                              void* d_out, int out_size)
{
    const float* x  = (const float*)d_in[0];
    const float* Wa = (const float*)d_in[1];
    const float* ba = (const float*)d_in[2];
    const float* Wb = (const float*)d_in[3];
    const float* bb = (const float*)d_in[4];
    const float* Wc = (const float*)d_in[5];
    const float* bc = (const float*)d_in[6];
    const float* Wo = (const float*)d_in[7];
    const float* bo = (const float*)d_in[8];
    float* out = (float*)d_out;

    cudaFuncSetAttribute(tc_gemm_ab,   cudaFuncAttributeMaxDynamicSharedMemorySize, GEMM_SMEM);
    cudaFuncSetAttribute(tc_gemm_main, cudaFuncAttributeMaxDynamicSharedMemorySize, GEMM_SMEM);

    pool_convert<<<PB * PLS * 64 / 256, 256>>>(x);
    prep_w<<<dim3(8, 8, 3), dim3(32, 8)>>>(Wa, Wb, Wc);
    tc_gemm_ab<<<dim3(4, 256), 256, GEMM_SMEM>>>(ba, bb);
    softmax_reduce<<<PB * PCOUT, 256>>>();
    build_weff<<<dim3(4, 4, PB), 256>>>(Wo);
    build_beff<<<PB, 256>>>(bc, Wo, bo);
    tc_gemm_main<<<dim3(2, 1024), 256, GEMM_SMEM>>>(out);
}